// round 2
// baseline (speedup 1.0000x reference)
#include <cuda_runtime.h>

#define N_NODES 20000
#define E_EDGES 320000
#define E_TOT   (E_EDGES + N_NODES)   // self-loops appended
#define IN_C    256
#define HID     64
#define HEADS   4
#define OUT_C   64
#define F1      (HEADS * HID)         // 256

// ---------------- scratch (device globals, no allocs) ----------------
__device__ float g_h1[(size_t)N_NODES * F1];     // layer1 transformed features
__device__ float g_out1[(size_t)N_NODES * F1];   // layer1 aggregated output (pre-ELU)
__device__ float g_h2[(size_t)N_NODES * OUT_C];  // layer2 transformed features
__device__ float g_e1s[N_NODES * HEADS];
__device__ float g_e1d[N_NODES * HEADS];
__device__ float g_z1[N_NODES * HEADS];
__device__ float g_e2s[N_NODES];
__device__ float g_e2d[N_NODES];
__device__ float g_z2[N_NODES];
__device__ float g_p1[(size_t)E_TOT * HEADS];
__device__ float g_p2[E_TOT];

// ---------------- init: zero accumulators, broadcast biases ----------------
__global__ void init_kernel(float* __restrict__ out1, float* __restrict__ dout,
                            float* __restrict__ z1, float* __restrict__ z2,
                            const float* __restrict__ b1, const float* __restrict__ b2) {
    int i = blockIdx.x * blockDim.x + threadIdx.x;
    int tot = N_NODES * F1;
    if (i < tot) out1[i] = b1[i & (F1 - 1)];
    if (i < N_NODES * OUT_C) dout[i] = b2[i & (OUT_C - 1)];
    if (i < N_NODES * HEADS) z1[i] = 0.f;
    if (i < N_NODES) z2[i] = 0.f;
}

// ---------------- tiled SGEMM: C[M,N] = op(A)[M,K] @ B[K,N] ----------------
// BM=128, BN=64, BK=16, 256 threads, each computes 8x4. ELU_A applies elu on A load.
template<bool ELU_A>
__global__ void sgemm_kernel(const float* __restrict__ A, const float* __restrict__ B,
                             float* __restrict__ C, int M, int N, int K) {
    __shared__ float As[16][128];
    __shared__ float Bs[16][64];
    const int bm = blockIdx.y * 128;
    const int bn = blockIdx.x * 64;
    const int tid = threadIdx.x;
    const int tn = (tid & 15) * 4;
    const int tm = (tid >> 4) * 8;

    float acc[8][4];
    #pragma unroll
    for (int i = 0; i < 8; i++)
        #pragma unroll
        for (int j = 0; j < 4; j++) acc[i][j] = 0.f;

    for (int k0 = 0; k0 < K; k0 += 16) {
        // A tile: 128 rows x 16 cols; thread loads 8 consecutive k at one row
        {
            int r = tid >> 1;
            int c = (tid & 1) * 8;
            const float* src = A + (size_t)(bm + r) * K + k0 + c;
            bool inb = (bm + r) < M;
            #pragma unroll
            for (int i = 0; i < 8; i++) {
                float v = inb ? src[i] : 0.f;
                if (ELU_A) v = v > 0.f ? v : expm1f(v);
                As[c + i][r] = v;
            }
        }
        // B tile: 16 rows x 64 cols
        {
            int r = tid >> 4;
            int c = (tid & 15) * 4;
            float4 v = *(const float4*)(B + (size_t)(k0 + r) * N + bn + c);
            *(float4*)&Bs[r][c] = v;
        }
        __syncthreads();
        #pragma unroll
        for (int kk = 0; kk < 16; kk++) {
            float a[8], b[4];
            #pragma unroll
            for (int i = 0; i < 8; i++) a[i] = As[kk][tm + i];
            #pragma unroll
            for (int j = 0; j < 4; j++) b[j] = Bs[kk][tn + j];
            #pragma unroll
            for (int i = 0; i < 8; i++)
                #pragma unroll
                for (int j = 0; j < 4; j++) acc[i][j] += a[i] * b[j];
        }
        __syncthreads();
    }
    #pragma unroll
    for (int i = 0; i < 8; i++) {
        int m = bm + tm + i;
        if (m < M) {
            float4 v = make_float4(acc[i][0], acc[i][1], acc[i][2], acc[i][3]);
            *(float4*)(C + (size_t)m * N + bn + tn) = v;
        }
    }
}

// ---------------- per-node attention dot products (warp per node) ----------------
__global__ void edot_kernel(const float* __restrict__ h,
                            const float* __restrict__ a_src, const float* __restrict__ a_dst,
                            float* __restrict__ es, float* __restrict__ ed,
                            int n, int heads) {
    int warp = (blockIdx.x * blockDim.x + threadIdx.x) >> 5;
    int lane = threadIdx.x & 31;
    if (warp >= n) return;
    const float* row = h + (size_t)warp * heads * 64;
    for (int hh = 0; hh < heads; hh++) {
        float v0 = row[hh * 64 + lane];
        float v1 = row[hh * 64 + lane + 32];
        float s = v0 * a_src[hh * 64 + lane] + v1 * a_src[hh * 64 + lane + 32];
        float d = v0 * a_dst[hh * 64 + lane] + v1 * a_dst[hh * 64 + lane + 32];
        #pragma unroll
        for (int o = 16; o; o >>= 1) {
            s += __shfl_xor_sync(0xFFFFFFFFu, s, o);
            d += __shfl_xor_sync(0xFFFFFFFFu, d, o);
        }
        if (lane == 0) {
            es[warp * heads + hh] = s;
            ed[warp * heads + hh] = d;
        }
    }
}

// ---------------- edge pass: p = exp(leakyrelu(es[src]+ed[dst])), z[dst] += p ----------------
__global__ void edge_p_kernel(const int* __restrict__ ei,
                              const float* __restrict__ es, const float* __restrict__ ed,
                              float* __restrict__ p, float* __restrict__ z, int heads) {
    int e = blockIdx.x * blockDim.x + threadIdx.x;
    if (e >= E_TOT) return;
    int s = (e < E_EDGES) ? ei[e] : (e - E_EDGES);
    int d = (e < E_EDGES) ? ei[E_EDGES + e] : (e - E_EDGES);
    for (int hh = 0; hh < heads; hh++) {
        float l = es[s * heads + hh] + ed[d * heads + hh];
        l = l > 0.f ? l : 0.2f * l;
        float pe = expf(l);
        p[(size_t)e * heads + hh] = pe;
        atomicAdd(&z[d * heads + hh], pe);
    }
}

// ---------------- layer-1 scatter: warp per edge, 256 channels ----------------
__global__ void scatter1_kernel(const int* __restrict__ ei,
                                const float* __restrict__ h, const float* __restrict__ p,
                                const float* __restrict__ z, float* __restrict__ out) {
    int e = (blockIdx.x * blockDim.x + threadIdx.x) >> 5;
    int lane = threadIdx.x & 31;
    if (e >= E_TOT) return;
    int s = (e < E_EDGES) ? ei[e] : (e - E_EDGES);
    int d = (e < E_EDGES) ? ei[E_EDGES + e] : (e - E_EDGES);
    float alpha[HEADS];
    #pragma unroll
    for (int hh = 0; hh < HEADS; hh++)
        alpha[hh] = p[(size_t)e * HEADS + hh] / z[d * HEADS + hh];
    const float* hrow = h + (size_t)s * F1;
    float* orow = out + (size_t)d * F1;
    #pragma unroll
    for (int i = 0; i < 8; i++) {
        int c = lane + 32 * i;
        atomicAdd(&orow[c], hrow[c] * alpha[c >> 6]);
    }
}

// ---------------- layer-2 scatter: warp per edge, 64 channels ----------------
__global__ void scatter2_kernel(const int* __restrict__ ei,
                                const float* __restrict__ h2, const float* __restrict__ p,
                                const float* __restrict__ z, float* __restrict__ out) {
    int e = (blockIdx.x * blockDim.x + threadIdx.x) >> 5;
    int lane = threadIdx.x & 31;
    if (e >= E_TOT) return;
    int s = (e < E_EDGES) ? ei[e] : (e - E_EDGES);
    int d = (e < E_EDGES) ? ei[E_EDGES + e] : (e - E_EDGES);
    float alpha = p[e] / z[d];
    const float* hrow = h2 + (size_t)s * OUT_C;
    float* orow = out + (size_t)d * OUT_C;
    atomicAdd(&orow[lane], hrow[lane] * alpha);
    atomicAdd(&orow[lane + 32], hrow[lane + 32] * alpha);
}

extern "C" void kernel_launch(void* const* d_in, const int* in_sizes, int n_in,
                              void* d_out, int out_size) {
    const float* x    = (const float*)d_in[0];
    const int*   ei   = (const int*)d_in[1];   // int32: JAX default (x64 disabled)
    const float* W1   = (const float*)d_in[2];
    const float* a1s  = (const float*)d_in[3];
    const float* a1d  = (const float*)d_in[4];
    const float* b1   = (const float*)d_in[5];
    const float* W2   = (const float*)d_in[6];
    const float* a2s  = (const float*)d_in[7];
    const float* a2d  = (const float*)d_in[8];
    const float* b2   = (const float*)d_in[9];
    float* out = (float*)d_out;

    float *h1, *out1, *h2, *e1s, *e1d, *z1, *e2s, *e2d, *z2, *p1, *p2;
    cudaGetSymbolAddress((void**)&h1,  g_h1);
    cudaGetSymbolAddress((void**)&out1, g_out1);
    cudaGetSymbolAddress((void**)&h2,  g_h2);
    cudaGetSymbolAddress((void**)&e1s, g_e1s);
    cudaGetSymbolAddress((void**)&e1d, g_e1d);
    cudaGetSymbolAddress((void**)&z1,  g_z1);
    cudaGetSymbolAddress((void**)&e2s, g_e2s);
    cudaGetSymbolAddress((void**)&e2d, g_e2d);
    cudaGetSymbolAddress((void**)&z2,  g_z2);
    cudaGetSymbolAddress((void**)&p1,  g_p1);
    cudaGetSymbolAddress((void**)&p2,  g_p2);

    // init accumulators / biases
    {
        int tot = N_NODES * F1;
        init_kernel<<<(tot + 255) / 256, 256>>>(out1, out, z1, z2, b1, b2);
    }

    // Layer 1
    {
        dim3 grid((F1 + 63) / 64, (N_NODES + 127) / 128);
        sgemm_kernel<false><<<grid, 256>>>(x, W1, h1, N_NODES, F1, IN_C);
    }
    edot_kernel<<<(N_NODES * 32 + 255) / 256, 256>>>(h1, a1s, a1d, e1s, e1d, N_NODES, HEADS);
    edge_p_kernel<<<(E_TOT + 255) / 256, 256>>>(ei, e1s, e1d, p1, z1, HEADS);
    scatter1_kernel<<<(E_TOT * 32 + 255) / 256, 256>>>(ei, h1, p1, z1, out1);

    // Layer 2 (ELU fused into GEMM A-load)
    {
        dim3 grid((OUT_C + 63) / 64, (N_NODES + 127) / 128);
        sgemm_kernel<true><<<grid, 256>>>(out1, W2, h2, N_NODES, OUT_C, F1);
    }
    edot_kernel<<<(N_NODES * 32 + 255) / 256, 256>>>(h2, a2s, a2d, e2s, e2d, N_NODES, 1);
    edge_p_kernel<<<(E_TOT + 255) / 256, 256>>>(ei, e2s, e2d, p2, z2, 1);
    scatter2_kernel<<<(E_TOT * 32 + 255) / 256, 256>>>(ei, h2, p2, z2, out);
}

// round 3
// speedup vs baseline: 1.1023x; 1.1023x over previous
#include <cuda_runtime.h>

#define N_NODES 20000
#define E_EDGES 320000
#define E_TOT   (E_EDGES + N_NODES)   // self-loops appended
#define IN_C    256
#define HID     64
#define HEADS   4
#define OUT_C   64
#define F1      (HEADS * HID)         // 256

// ---------------- scratch (device globals, no allocs) ----------------
__device__ float g_h1[(size_t)N_NODES * F1];     // layer1 transformed features
__device__ float g_out1[(size_t)N_NODES * F1];   // layer1 UNNORMALIZED aggregate
__device__ float g_h2[(size_t)N_NODES * OUT_C];  // layer2 transformed features
__device__ float g_e1s[N_NODES * HEADS];
__device__ float g_e1d[N_NODES * HEADS];
__device__ float g_z1[N_NODES * HEADS];
__device__ float g_e2s[N_NODES];
__device__ float g_e2d[N_NODES];
__device__ float g_z2[N_NODES];

// ---------------- packed f32x2 helpers ----------------
__device__ __forceinline__ unsigned long long pack2(float lo, float hi) {
    unsigned long long r;
    asm("mov.b64 %0, {%1, %2};" : "=l"(r) : "f"(lo), "f"(hi));
    return r;
}
__device__ __forceinline__ void unpack2(unsigned long long v, float& lo, float& hi) {
    asm("mov.b64 {%0, %1}, %2;" : "=f"(lo), "=f"(hi) : "l"(v));
}
__device__ __forceinline__ unsigned long long fma2(unsigned long long a,
                                                   unsigned long long b,
                                                   unsigned long long c) {
    unsigned long long d;
    asm("fma.rn.f32x2 %0, %1, %2, %3;" : "=l"(d) : "l"(a), "l"(b), "l"(c));
    return d;
}
__device__ __forceinline__ void red_add_v4(float* p, float4 v) {
    asm volatile("red.global.add.v4.f32 [%0], {%1, %2, %3, %4};"
                 :: "l"(p), "f"(v.x), "f"(v.y), "f"(v.z), "f"(v.w) : "memory");
}
__device__ __forceinline__ void red_add_f32(float* p, float v) {
    asm volatile("red.global.add.f32 [%0], %1;" :: "l"(p), "f"(v) : "memory");
}

// ---------------- init: zero accumulators ----------------
__global__ void init_kernel(float* __restrict__ out1, float* __restrict__ dout,
                            float* __restrict__ z1, float* __restrict__ z2) {
    int i = blockIdx.x * blockDim.x + threadIdx.x;
    if (i < N_NODES * F1) out1[i] = 0.f;
    if (i < N_NODES * OUT_C) dout[i] = 0.f;
    if (i < N_NODES * HEADS) z1[i] = 0.f;
    if (i < N_NODES) z2[i] = 0.f;
}

// ---------------- packed-f32x2 SGEMM: C[M,N] = op(A)[M,K] @ B[K,N] ----------------
// BM=128, BN=64, BK=16, 128 threads, each thread computes 8x8 via f32x2 pairs.
// NORM_ELU: A-row r is first transformed v = elu(v / Z[r*4+head] + bias[k]).
template<bool NORM_ELU>
__global__ void __launch_bounds__(128)
sgemm2_kernel(const float* __restrict__ A, const float* __restrict__ B,
              float* __restrict__ C, int M, int N, int K,
              const float* __restrict__ Z, const float* __restrict__ bias) {
    __shared__ float As[16][132];   // padded
    __shared__ float Bs[16][68];
    const int bm = blockIdx.y * 128;
    const int bn = blockIdx.x * 64;
    const int tid = threadIdx.x;
    const int tm = (tid >> 3) * 8;   // 16 groups * 8 = 128 m
    const int tn = (tid & 7) * 8;    // 8 groups * 8 = 64 n

    unsigned long long acc[8][4];
    #pragma unroll
    for (int i = 0; i < 8; i++)
        #pragma unroll
        for (int j = 0; j < 4; j++) acc[i][j] = 0ull;

    for (int k0 = 0; k0 < K; k0 += 16) {
        // ---- A tile: each thread loads one row (tid) x 16 k, transposes into As
        {
            int r = tid;
            int row = bm + r;
            float inv_z = 1.f;
            if (NORM_ELU) {
                int head = k0 >> 6;   // constant across 16-wide k-tile (64 % 16 == 0)
                if (row < M) inv_z = 1.f / Z[row * 4 + head];
            }
            #pragma unroll
            for (int cc = 0; cc < 4; cc++) {
                int c = cc * 4;
                float4 v = make_float4(0.f, 0.f, 0.f, 0.f);
                if (row < M) v = *(const float4*)(A + (size_t)row * K + k0 + c);
                if (NORM_ELU) {
                    float b0 = bias[k0 + c + 0], b1 = bias[k0 + c + 1];
                    float b2 = bias[k0 + c + 2], b3 = bias[k0 + c + 3];
                    v.x = v.x * inv_z + b0; v.x = v.x > 0.f ? v.x : expm1f(v.x);
                    v.y = v.y * inv_z + b1; v.y = v.y > 0.f ? v.y : expm1f(v.y);
                    v.z = v.z * inv_z + b2; v.z = v.z > 0.f ? v.z : expm1f(v.z);
                    v.w = v.w * inv_z + b3; v.w = v.w > 0.f ? v.w : expm1f(v.w);
                }
                As[c + 0][r] = v.x; As[c + 1][r] = v.y;
                As[c + 2][r] = v.z; As[c + 3][r] = v.w;
            }
        }
        // ---- B tile: 16 x 64; thread loads 8 floats
        {
            int r = tid >> 3;
            int c = (tid & 7) * 8;
            const float* src = B + (size_t)(k0 + r) * N + bn + c;
            *(float4*)&Bs[r][c] = *(const float4*)src;
            *(float4*)&Bs[r][c + 4] = *(const float4*)(src + 4);
        }
        __syncthreads();
        #pragma unroll
        for (int kk = 0; kk < 16; kk++) {
            float a[8];
            *(float4*)&a[0] = *(const float4*)&As[kk][tm];
            *(float4*)&a[4] = *(const float4*)&As[kk][tm + 4];
            unsigned long long b2v[4];
            float bl[8];
            *(float4*)&bl[0] = *(const float4*)&Bs[kk][tn];
            *(float4*)&bl[4] = *(const float4*)&Bs[kk][tn + 4];
            #pragma unroll
            for (int j = 0; j < 4; j++) b2v[j] = pack2(bl[2 * j], bl[2 * j + 1]);
            #pragma unroll
            for (int i = 0; i < 8; i++) {
                unsigned long long a2 = pack2(a[i], a[i]);
                #pragma unroll
                for (int j = 0; j < 4; j++) acc[i][j] = fma2(a2, b2v[j], acc[i][j]);
            }
        }
        __syncthreads();
    }
    #pragma unroll
    for (int i = 0; i < 8; i++) {
        int m = bm + tm + i;
        if (m < M) {
            float o[8];
            #pragma unroll
            for (int j = 0; j < 4; j++) unpack2(acc[i][j], o[2 * j], o[2 * j + 1]);
            float* dst = C + (size_t)m * N + bn + tn;
            *(float4*)dst = *(float4*)&o[0];
            *(float4*)(dst + 4) = *(float4*)&o[4];
        }
    }
}

// ---------------- per-node attention dot products (warp per node) ----------------
__global__ void edot_kernel(const float* __restrict__ h,
                            const float* __restrict__ a_src, const float* __restrict__ a_dst,
                            float* __restrict__ es, float* __restrict__ ed,
                            int n, int heads) {
    int warp = (blockIdx.x * blockDim.x + threadIdx.x) >> 5;
    int lane = threadIdx.x & 31;
    if (warp >= n) return;
    const float* row = h + (size_t)warp * heads * 64;
    for (int hh = 0; hh < heads; hh++) {
        float v0 = row[hh * 64 + lane];
        float v1 = row[hh * 64 + lane + 32];
        float s = v0 * a_src[hh * 64 + lane] + v1 * a_src[hh * 64 + lane + 32];
        float d = v0 * a_dst[hh * 64 + lane] + v1 * a_dst[hh * 64 + lane + 32];
        #pragma unroll
        for (int o = 16; o; o >>= 1) {
            s += __shfl_xor_sync(0xFFFFFFFFu, s, o);
            d += __shfl_xor_sync(0xFFFFFFFFu, d, o);
        }
        if (lane == 0) {
            es[warp * heads + hh] = s;
            ed[warp * heads + hh] = d;
        }
    }
}

// ---------------- fused edge pass layer 1: warp per edge ----------------
// p_h = exp(leakyrelu(es[s,h]+ed[d,h]));  z[d,h] += p_h;  out[d,:] += p_h * h1[s,:]
__global__ void edge1_kernel(const int* __restrict__ ei,
                             const float* __restrict__ es, const float* __restrict__ ed,
                             const float* __restrict__ h, float* __restrict__ z,
                             float* __restrict__ out) {
    int e = (blockIdx.x * blockDim.x + threadIdx.x) >> 5;
    int lane = threadIdx.x & 31;
    if (e >= E_TOT) return;
    int s = (e < E_EDGES) ? ei[e] : (e - E_EDGES);
    int d = (e < E_EDGES) ? ei[E_EDGES + e] : (e - E_EDGES);
    float p = 0.f;
    if (lane < HEADS) {
        float l = es[s * HEADS + lane] + ed[d * HEADS + lane];
        l = l > 0.f ? l : 0.2f * l;
        p = expf(l);
        red_add_f32(&z[d * HEADS + lane], p);
    }
    float p0 = __shfl_sync(0xFFFFFFFFu, p, 0);
    float p1 = __shfl_sync(0xFFFFFFFFu, p, 1);
    float p2 = __shfl_sync(0xFFFFFFFFu, p, 2);
    float p3 = __shfl_sync(0xFFFFFFFFu, p, 3);
    const float4* hr = (const float4*)(h + (size_t)s * F1);
    float* orow = out + (size_t)d * F1;
    #pragma unroll
    for (int j = 0; j < 2; j++) {
        int c4 = lane + 32 * j;            // 0..63 float4 chunks
        int head = c4 >> 4;
        float ph = head == 0 ? p0 : head == 1 ? p1 : head == 2 ? p2 : p3;
        float4 hv = hr[c4];
        hv.x *= ph; hv.y *= ph; hv.z *= ph; hv.w *= ph;
        red_add_v4(orow + c4 * 4, hv);
    }
}

// ---------------- fused edge pass layer 2 (1 head, 64 ch): warp per edge ----------------
__global__ void edge2_kernel(const int* __restrict__ ei,
                             const float* __restrict__ es, const float* __restrict__ ed,
                             const float* __restrict__ h2, float* __restrict__ z,
                             float* __restrict__ out) {
    int e = (blockIdx.x * blockDim.x + threadIdx.x) >> 5;
    int lane = threadIdx.x & 31;
    if (e >= E_TOT) return;
    int s = (e < E_EDGES) ? ei[e] : (e - E_EDGES);
    int d = (e < E_EDGES) ? ei[E_EDGES + e] : (e - E_EDGES);
    float l = es[s] + ed[d];
    l = l > 0.f ? l : 0.2f * l;
    float p = expf(l);
    if (lane == 0) red_add_f32(&z[d], p);
    if (lane < 16) {
        const float4* hr = (const float4*)(h2 + (size_t)s * OUT_C);
        float4 hv = hr[lane];
        hv.x *= p; hv.y *= p; hv.z *= p; hv.w *= p;
        red_add_v4(out + (size_t)d * OUT_C + lane * 4, hv);
    }
}

// ---------------- final: out = raw/z2 + b2 ----------------
__global__ void final_kernel(float* __restrict__ out, const float* __restrict__ z2,
                             const float* __restrict__ b2) {
    int i = blockIdx.x * blockDim.x + threadIdx.x;
    if (i >= N_NODES * OUT_C) return;
    out[i] = out[i] / z2[i >> 6] + b2[i & 63];
}

extern "C" void kernel_launch(void* const* d_in, const int* in_sizes, int n_in,
                              void* d_out, int out_size) {
    const float* x    = (const float*)d_in[0];
    const int*   ei   = (const int*)d_in[1];   // int32 (JAX default x64 disabled)
    const float* W1   = (const float*)d_in[2];
    const float* a1s  = (const float*)d_in[3];
    const float* a1d  = (const float*)d_in[4];
    const float* b1   = (const float*)d_in[5];
    const float* W2   = (const float*)d_in[6];
    const float* a2s  = (const float*)d_in[7];
    const float* a2d  = (const float*)d_in[8];
    const float* b2   = (const float*)d_in[9];
    float* out = (float*)d_out;

    float *h1, *out1, *h2, *e1s, *e1d, *z1, *e2s, *e2d, *z2;
    cudaGetSymbolAddress((void**)&h1,  g_h1);
    cudaGetSymbolAddress((void**)&out1, g_out1);
    cudaGetSymbolAddress((void**)&h2,  g_h2);
    cudaGetSymbolAddress((void**)&e1s, g_e1s);
    cudaGetSymbolAddress((void**)&e1d, g_e1d);
    cudaGetSymbolAddress((void**)&z1,  g_z1);
    cudaGetSymbolAddress((void**)&e2s, g_e2s);
    cudaGetSymbolAddress((void**)&e2d, g_e2d);
    cudaGetSymbolAddress((void**)&z2,  g_z2);

    // init accumulators
    init_kernel<<<(N_NODES * F1 + 255) / 256, 256>>>(out1, out, z1, z2);

    // Layer 1
    {
        dim3 grid(F1 / 64, (N_NODES + 127) / 128);
        sgemm2_kernel<false><<<grid, 128>>>(x, W1, h1, N_NODES, F1, IN_C, nullptr, nullptr);
    }
    edot_kernel<<<(N_NODES * 32 + 255) / 256, 256>>>(h1, a1s, a1d, e1s, e1d, N_NODES, HEADS);
    edge1_kernel<<<(E_TOT * 32 + 255) / 256, 256>>>(ei, e1s, e1d, h1, z1, out1);

    // Layer 2: normalize + bias + ELU fused into GEMM A-load
    {
        dim3 grid(OUT_C / 64, (N_NODES + 127) / 128);
        sgemm2_kernel<true><<<grid, 128>>>(out1, W2, h2, N_NODES, OUT_C, F1, z1, b1);
    }
    edot_kernel<<<(N_NODES * 32 + 255) / 256, 256>>>(h2, a2s, a2d, e2s, e2d, N_NODES, 1);
    edge2_kernel<<<(E_TOT * 32 + 255) / 256, 256>>>(ei, e2s, e2d, h2, z2, out);

    final_kernel<<<(N_NODES * OUT_C + 255) / 256, 256>>>(out, z2, b2);
}

// round 4
// speedup vs baseline: 1.2993x; 1.1787x over previous
#include <cuda_runtime.h>

#define N_NODES 20000
#define E_EDGES 320000
#define E_TOT   (E_EDGES + N_NODES)   // self-loops appended
#define IN_C    256
#define HID     64
#define HEADS   4
#define OUT_C   64
#define F1      (HEADS * HID)         // 256

// ---------------- scratch (device globals, no allocs) ----------------
__device__ float g_h1[(size_t)N_NODES * F1];     // layer1 transformed features
__device__ float g_out1[(size_t)N_NODES * F1];   // layer1 output (normalized + bias + ELU)
__device__ float g_h2[(size_t)N_NODES * OUT_C];  // layer2 transformed features
__device__ float g_e1s[N_NODES * HEADS];
__device__ float g_e1d[N_NODES * HEADS];
__device__ float g_e2s[N_NODES];
__device__ float g_e2d[N_NODES];
__device__ int   g_cnt[N_NODES];
__device__ int   g_off[N_NODES + 1];
__device__ int   g_cursor[N_NODES];
__device__ int   g_csr[E_TOT];

// ---------------- packed f32x2 helpers ----------------
__device__ __forceinline__ unsigned long long pack2(float lo, float hi) {
    unsigned long long r;
    asm("mov.b64 %0, {%1, %2};" : "=l"(r) : "f"(lo), "f"(hi));
    return r;
}
__device__ __forceinline__ void unpack2(unsigned long long v, float& lo, float& hi) {
    asm("mov.b64 {%0, %1}, %2;" : "=f"(lo), "=f"(hi) : "l"(v));
}
__device__ __forceinline__ unsigned long long fma2(unsigned long long a,
                                                   unsigned long long b,
                                                   unsigned long long c) {
    unsigned long long d;
    asm("fma.rn.f32x2 %0, %1, %2, %3;" : "=l"(d) : "l"(a), "l"(b), "l"(c));
    return d;
}

// ================= CSR build =================
__global__ void initcnt_kernel(int* __restrict__ cnt) {
    int i = blockIdx.x * blockDim.x + threadIdx.x;
    if (i < N_NODES) cnt[i] = 1;   // self-loop
}
__global__ void count_kernel(const int* __restrict__ ei, int* __restrict__ cnt) {
    int e = blockIdx.x * blockDim.x + threadIdx.x;
    if (e < E_EDGES) atomicAdd(&cnt[ei[E_EDGES + e]], 1);
}
// single-block exclusive scan of cnt[0..N) -> off and cursor
__global__ void __launch_bounds__(1024) scan_kernel(const int* __restrict__ cnt,
                                                    int* __restrict__ off,
                                                    int* __restrict__ cursor) {
    __shared__ int partial[1024];
    const int CH = (N_NODES + 1023) / 1024;   // 20
    int tid = threadIdx.x;
    int base = tid * CH;
    int local[CH];
    int sum = 0;
    #pragma unroll
    for (int i = 0; i < CH; i++) {
        int idx = base + i;
        int v = idx < N_NODES ? cnt[idx] : 0;
        local[i] = sum;
        sum += v;
    }
    partial[tid] = sum;
    __syncthreads();
    for (int o = 1; o < 1024; o <<= 1) {
        int v = tid >= o ? partial[tid - o] : 0;
        __syncthreads();
        partial[tid] += v;
        __syncthreads();
    }
    int prev = tid ? partial[tid - 1] : 0;
    #pragma unroll
    for (int i = 0; i < CH; i++) {
        int idx = base + i;
        if (idx < N_NODES) {
            int v = prev + local[i];
            off[idx] = v;
            cursor[idx] = v;
        }
    }
    if (tid == 1023) off[N_NODES] = partial[1023];
}
__global__ void fill_kernel(const int* __restrict__ ei, int* __restrict__ cursor,
                            int* __restrict__ csr) {
    int e = blockIdx.x * blockDim.x + threadIdx.x;
    if (e >= E_TOT) return;
    int s, d;
    if (e < E_EDGES) { s = ei[e]; d = ei[E_EDGES + e]; }
    else { s = e - E_EDGES; d = s; }
    int pos = atomicAdd(&cursor[d], 1);
    csr[pos] = s;
}

// ---------------- packed-f32x2 SGEMM: C[M,N] = A[M,K] @ B[K,N] ----------------
__global__ void __launch_bounds__(128)
sgemm2_kernel(const float* __restrict__ A, const float* __restrict__ B,
              float* __restrict__ C, int M, int N, int K) {
    __shared__ float As[16][132];
    __shared__ float Bs[16][68];
    const int bm = blockIdx.y * 128;
    const int bn = blockIdx.x * 64;
    const int tid = threadIdx.x;
    const int tm = (tid >> 3) * 8;
    const int tn = (tid & 7) * 8;

    unsigned long long acc[8][4];
    #pragma unroll
    for (int i = 0; i < 8; i++)
        #pragma unroll
        for (int j = 0; j < 4; j++) acc[i][j] = 0ull;

    for (int k0 = 0; k0 < K; k0 += 16) {
        {
            int r = tid;
            int row = bm + r;
            #pragma unroll
            for (int cc = 0; cc < 4; cc++) {
                int c = cc * 4;
                float4 v = make_float4(0.f, 0.f, 0.f, 0.f);
                if (row < M) v = *(const float4*)(A + (size_t)row * K + k0 + c);
                As[c + 0][r] = v.x; As[c + 1][r] = v.y;
                As[c + 2][r] = v.z; As[c + 3][r] = v.w;
            }
        }
        {
            int r = tid >> 3;
            int c = (tid & 7) * 8;
            const float* src = B + (size_t)(k0 + r) * N + bn + c;
            *(float4*)&Bs[r][c] = *(const float4*)src;
            *(float4*)&Bs[r][c + 4] = *(const float4*)(src + 4);
        }
        __syncthreads();
        #pragma unroll
        for (int kk = 0; kk < 16; kk++) {
            float a[8];
            *(float4*)&a[0] = *(const float4*)&As[kk][tm];
            *(float4*)&a[4] = *(const float4*)&As[kk][tm + 4];
            unsigned long long b2v[4];
            float bl[8];
            *(float4*)&bl[0] = *(const float4*)&Bs[kk][tn];
            *(float4*)&bl[4] = *(const float4*)&Bs[kk][tn + 4];
            #pragma unroll
            for (int j = 0; j < 4; j++) b2v[j] = pack2(bl[2 * j], bl[2 * j + 1]);
            #pragma unroll
            for (int i = 0; i < 8; i++) {
                unsigned long long a2 = pack2(a[i], a[i]);
                #pragma unroll
                for (int j = 0; j < 4; j++) acc[i][j] = fma2(a2, b2v[j], acc[i][j]);
            }
        }
        __syncthreads();
    }
    #pragma unroll
    for (int i = 0; i < 8; i++) {
        int m = bm + tm + i;
        if (m < M) {
            float o[8];
            #pragma unroll
            for (int j = 0; j < 4; j++) unpack2(acc[i][j], o[2 * j], o[2 * j + 1]);
            float* dst = C + (size_t)m * N + bn + tn;
            *(float4*)dst = *(float4*)&o[0];
            *(float4*)(dst + 4) = *(float4*)&o[4];
        }
    }
}

// ---------------- per-node attention dot products (warp per node) ----------------
__global__ void edot_kernel(const float* __restrict__ h,
                            const float* __restrict__ a_src, const float* __restrict__ a_dst,
                            float* __restrict__ es, float* __restrict__ ed,
                            int n, int heads) {
    int warp = (blockIdx.x * blockDim.x + threadIdx.x) >> 5;
    int lane = threadIdx.x & 31;
    if (warp >= n) return;
    const float* row = h + (size_t)warp * heads * 64;
    for (int hh = 0; hh < heads; hh++) {
        float v0 = row[hh * 64 + lane];
        float v1 = row[hh * 64 + lane + 32];
        float s = v0 * a_src[hh * 64 + lane] + v1 * a_src[hh * 64 + lane + 32];
        float d = v0 * a_dst[hh * 64 + lane] + v1 * a_dst[hh * 64 + lane + 32];
        #pragma unroll
        for (int o = 16; o; o >>= 1) {
            s += __shfl_xor_sync(0xFFFFFFFFu, s, o);
            d += __shfl_xor_sync(0xFFFFFFFFu, d, o);
        }
        if (lane == 0) {
            es[warp * heads + hh] = s;
            ed[warp * heads + hh] = d;
        }
    }
}

// ---------------- layer-1 pull aggregation: warp per (node, head) ----------------
// out1[n, head*64:(head+1)*64] = elu( (Σ_e p_e h1[src_e]) / Σ_e p_e + b1 )
__global__ void agg1_kernel(const int* __restrict__ off, const int* __restrict__ csr,
                            const float* __restrict__ h,
                            const float* __restrict__ es, const float* __restrict__ ed,
                            const float* __restrict__ b1, float* __restrict__ out) {
    int gw = (blockIdx.x * blockDim.x + threadIdx.x) >> 5;
    int lane = threadIdx.x & 31;
    if (gw >= N_NODES * HEADS) return;
    int n = gw >> 2, head = gw & 3;
    int beg = off[n], end = off[n + 1];
    float edn = ed[n * HEADS + head];
    float accx = 0.f, accy = 0.f, zsum = 0.f;
    for (int base = beg; base < end; base += 32) {
        int m = min(32, end - base);
        int sl = 0; float pl = 0.f;
        if (base + lane < end) {
            sl = csr[base + lane];
            float l = es[sl * HEADS + head] + edn;
            l = l > 0.f ? l : 0.2f * l;
            pl = expf(l);
        }
        for (int j = 0; j < m; j++) {
            int s = __shfl_sync(0xFFFFFFFFu, sl, j);
            float p = __shfl_sync(0xFFFFFFFFu, pl, j);
            zsum += p;
            float2 v = *(const float2*)(h + (size_t)s * F1 + head * 64 + lane * 2);
            accx += p * v.x;
            accy += p * v.y;
        }
    }
    float inv = 1.f / zsum;
    int c = head * 64 + lane * 2;
    float o0 = accx * inv + b1[c];
    float o1 = accy * inv + b1[c + 1];
    o0 = o0 > 0.f ? o0 : expm1f(o0);
    o1 = o1 > 0.f ? o1 : expm1f(o1);
    float2 r; r.x = o0; r.y = o1;
    *(float2*)(out + (size_t)n * F1 + c) = r;
}

// ---------------- layer-2 pull aggregation: warp per node ----------------
__global__ void agg2_kernel(const int* __restrict__ off, const int* __restrict__ csr,
                            const float* __restrict__ h2,
                            const float* __restrict__ es, const float* __restrict__ ed,
                            const float* __restrict__ b2, float* __restrict__ out) {
    int n = (blockIdx.x * blockDim.x + threadIdx.x) >> 5;
    int lane = threadIdx.x & 31;
    if (n >= N_NODES) return;
    int beg = off[n], end = off[n + 1];
    float edn = ed[n];
    float accx = 0.f, accy = 0.f, zsum = 0.f;
    for (int base = beg; base < end; base += 32) {
        int m = min(32, end - base);
        int sl = 0; float pl = 0.f;
        if (base + lane < end) {
            sl = csr[base + lane];
            float l = es[sl] + edn;
            l = l > 0.f ? l : 0.2f * l;
            pl = expf(l);
        }
        for (int j = 0; j < m; j++) {
            int s = __shfl_sync(0xFFFFFFFFu, sl, j);
            float p = __shfl_sync(0xFFFFFFFFu, pl, j);
            zsum += p;
            float2 v = *(const float2*)(h2 + (size_t)s * OUT_C + lane * 2);
            accx += p * v.x;
            accy += p * v.y;
        }
    }
    float inv = 1.f / zsum;
    float2 r;
    r.x = accx * inv + b2[lane * 2];
    r.y = accy * inv + b2[lane * 2 + 1];
    *(float2*)(out + (size_t)n * OUT_C + lane * 2) = r;
}

extern "C" void kernel_launch(void* const* d_in, const int* in_sizes, int n_in,
                              void* d_out, int out_size) {
    const float* x    = (const float*)d_in[0];
    const int*   ei   = (const int*)d_in[1];   // int32 (JAX default x64 disabled)
    const float* W1   = (const float*)d_in[2];
    const float* a1s  = (const float*)d_in[3];
    const float* a1d  = (const float*)d_in[4];
    const float* b1   = (const float*)d_in[5];
    const float* W2   = (const float*)d_in[6];
    const float* a2s  = (const float*)d_in[7];
    const float* a2d  = (const float*)d_in[8];
    const float* b2   = (const float*)d_in[9];
    float* out = (float*)d_out;

    float *h1, *out1, *h2, *e1s, *e1d, *e2s, *e2d;
    int *cnt, *off, *cursor, *csr;
    cudaGetSymbolAddress((void**)&h1,  g_h1);
    cudaGetSymbolAddress((void**)&out1, g_out1);
    cudaGetSymbolAddress((void**)&h2,  g_h2);
    cudaGetSymbolAddress((void**)&e1s, g_e1s);
    cudaGetSymbolAddress((void**)&e1d, g_e1d);
    cudaGetSymbolAddress((void**)&e2s, g_e2s);
    cudaGetSymbolAddress((void**)&e2d, g_e2d);
    cudaGetSymbolAddress((void**)&cnt, g_cnt);
    cudaGetSymbolAddress((void**)&off, g_off);
    cudaGetSymbolAddress((void**)&cursor, g_cursor);
    cudaGetSymbolAddress((void**)&csr, g_csr);

    // ---- CSR build (reused by both layers) ----
    initcnt_kernel<<<(N_NODES + 255) / 256, 256>>>(cnt);
    count_kernel<<<(E_EDGES + 255) / 256, 256>>>(ei, cnt);
    scan_kernel<<<1, 1024>>>(cnt, off, cursor);
    fill_kernel<<<(E_TOT + 255) / 256, 256>>>(ei, cursor, csr);

    // ---- Layer 1 ----
    {
        dim3 grid(F1 / 64, (N_NODES + 127) / 128);
        sgemm2_kernel<<<grid, 128>>>(x, W1, h1, N_NODES, F1, IN_C);
    }
    edot_kernel<<<(N_NODES * 32 + 255) / 256, 256>>>(h1, a1s, a1d, e1s, e1d, N_NODES, HEADS);
    agg1_kernel<<<(N_NODES * HEADS * 32 + 255) / 256, 256>>>(off, csr, h1, e1s, e1d, b1, out1);

    // ---- Layer 2 ----
    {
        dim3 grid(OUT_C / 64, (N_NODES + 127) / 128);
        sgemm2_kernel<<<grid, 128>>>(out1, W2, h2, N_NODES, OUT_C, F1);
    }
    edot_kernel<<<(N_NODES * 32 + 255) / 256, 256>>>(h2, a2s, a2d, e2s, e2d, N_NODES, 1);
    agg2_kernel<<<(N_NODES * 32 + 255) / 256, 256>>>(off, csr, h2, e2s, e2d, b2, out);
}

// round 5
// speedup vs baseline: 1.3067x; 1.0057x over previous
#include <cuda_runtime.h>

#define N_NODES 20000
#define E_EDGES 320000
#define E_TOT   (E_EDGES + N_NODES)
#define IN_C    256
#define HID     64
#define HEADS   4
#define OUT_C   64
#define F1      (HEADS * HID)         // 256

// ---------------- scratch (device globals, no allocs) ----------------
__device__ float g_h1[(size_t)N_NODES * F1];
__device__ float g_out1[(size_t)N_NODES * F1];
__device__ float g_h2[(size_t)N_NODES * OUT_C];
__device__ float g_e1s[N_NODES * HEADS];
__device__ float g_e1d[N_NODES * HEADS];
__device__ float g_e2s[N_NODES];
__device__ float g_e2d[N_NODES];
__device__ int   g_cnt[N_NODES];
__device__ int   g_off[N_NODES + 1];
__device__ int   g_cursor[N_NODES];
__device__ int   g_csr[E_TOT];

// ---------------- packed f32x2 helpers ----------------
__device__ __forceinline__ unsigned long long pack2(float lo, float hi) {
    unsigned long long r;
    asm("mov.b64 %0, {%1, %2};" : "=l"(r) : "f"(lo), "f"(hi));
    return r;
}
__device__ __forceinline__ void unpack2(unsigned long long v, float& lo, float& hi) {
    asm("mov.b64 {%0, %1}, %2;" : "=f"(lo), "=f"(hi) : "l"(v));
}
__device__ __forceinline__ unsigned long long fma2(unsigned long long a,
                                                   unsigned long long b,
                                                   unsigned long long c) {
    unsigned long long d;
    asm("fma.rn.f32x2 %0, %1, %2, %3;" : "=l"(d) : "l"(a), "l"(b), "l"(c));
    return d;
}

// ================= CSR build =================
__global__ void initcnt_kernel(int* __restrict__ cnt) {
    int i = blockIdx.x * blockDim.x + threadIdx.x;
    if (i < N_NODES) cnt[i] = 1;   // self-loop
}
// 4 edges per thread: independent atomics hide ATOMG latency
__global__ void count_kernel(const int* __restrict__ ei, int* __restrict__ cnt) {
    int e = (blockIdx.x * blockDim.x + threadIdx.x) * 4;
    if (e >= E_EDGES) return;
    int4 d4 = *(const int4*)(ei + E_EDGES + e);
    atomicAdd(&cnt[d4.x], 1);
    atomicAdd(&cnt[d4.y], 1);
    atomicAdd(&cnt[d4.z], 1);
    atomicAdd(&cnt[d4.w], 1);
}
// single-block scan (warp-shuffle based); also places self-loops into csr
__global__ void __launch_bounds__(1024) scan_kernel(const int* __restrict__ cnt,
                                                    int* __restrict__ off,
                                                    int* __restrict__ cursor,
                                                    int* __restrict__ csr) {
    __shared__ int wsum[32];
    const int CH = (N_NODES + 1023) / 1024;   // 20
    int tid = threadIdx.x;
    int lane = tid & 31, warp = tid >> 5;
    int base = tid * CH;
    int local[CH];
    int sum = 0;
    #pragma unroll
    for (int i = 0; i < CH; i++) {
        int idx = base + i;
        int v = idx < N_NODES ? cnt[idx] : 0;
        local[i] = sum;
        sum += v;
    }
    int inc = sum;
    #pragma unroll
    for (int o = 1; o < 32; o <<= 1) {
        int t = __shfl_up_sync(0xFFFFFFFFu, inc, o);
        if (lane >= o) inc += t;
    }
    if (lane == 31) wsum[warp] = inc;
    __syncthreads();
    if (warp == 0) {
        int w = wsum[lane];
        #pragma unroll
        for (int o = 1; o < 32; o <<= 1) {
            int t = __shfl_up_sync(0xFFFFFFFFu, w, o);
            if (lane >= o) w += t;
        }
        wsum[lane] = w;
    }
    __syncthreads();
    int prev = inc - sum + (warp ? wsum[warp - 1] : 0);
    #pragma unroll
    for (int i = 0; i < CH; i++) {
        int idx = base + i;
        if (idx < N_NODES) {
            int v = prev + local[i];
            off[idx] = v;
            cursor[idx] = v + 1;   // slot 0 taken by self-loop
            csr[v] = idx;          // self-loop
        }
    }
    if (tid == 1023) off[N_NODES] = prev + sum;
}
__global__ void fill_kernel(const int* __restrict__ ei, int* __restrict__ cursor,
                            int* __restrict__ csr) {
    int e = (blockIdx.x * blockDim.x + threadIdx.x) * 4;
    if (e >= E_EDGES) return;
    int4 s4 = *(const int4*)(ei + e);
    int4 d4 = *(const int4*)(ei + E_EDGES + e);
    csr[atomicAdd(&cursor[d4.x], 1)] = s4.x;
    csr[atomicAdd(&cursor[d4.y], 1)] = s4.y;
    csr[atomicAdd(&cursor[d4.z], 1)] = s4.z;
    csr[atomicAdd(&cursor[d4.w], 1)] = s4.w;
}

// ---------- packed-f32x2 SGEMM with fused attention-dot epilogue ----------
// C[M,N] = A[M,K] @ B[K,N]; BN=64 == one head's channels, so this block is the
// sole owner of (row, head): epilogue computes es/ed = C_row . a_src/a_dst directly.
// ESTRIDE = number of heads (es/ed row stride).
template<int ESTRIDE>
__global__ void __launch_bounds__(128)
sgemm2_kernel(const float* __restrict__ A, const float* __restrict__ B,
              float* __restrict__ C, int M, int K,
              const float* __restrict__ a_src, const float* __restrict__ a_dst,
              float* __restrict__ es, float* __restrict__ ed) {
    const int N = ESTRIDE * 64;
    __shared__ float As[16][132];
    __shared__ float Bs[16][68];
    const int bm = blockIdx.y * 128;
    const int bn = blockIdx.x * 64;
    const int head = bn >> 6;
    const int tid = threadIdx.x;
    const int tm = (tid >> 3) * 8;
    const int tn = (tid & 7) * 8;

    unsigned long long acc[8][4];
    #pragma unroll
    for (int i = 0; i < 8; i++)
        #pragma unroll
        for (int j = 0; j < 4; j++) acc[i][j] = 0ull;

    for (int k0 = 0; k0 < K; k0 += 16) {
        {
            int r = tid;
            int row = bm + r;
            #pragma unroll
            for (int cc = 0; cc < 4; cc++) {
                int c = cc * 4;
                float4 v = make_float4(0.f, 0.f, 0.f, 0.f);
                if (row < M) v = *(const float4*)(A + (size_t)row * K + k0 + c);
                As[c + 0][r] = v.x; As[c + 1][r] = v.y;
                As[c + 2][r] = v.z; As[c + 3][r] = v.w;
            }
        }
        {
            int r = tid >> 3;
            int c = (tid & 7) * 8;
            const float* src = B + (size_t)(k0 + r) * N + bn + c;
            *(float4*)&Bs[r][c] = *(const float4*)src;
            *(float4*)&Bs[r][c + 4] = *(const float4*)(src + 4);
        }
        __syncthreads();
        #pragma unroll
        for (int kk = 0; kk < 16; kk++) {
            float a[8];
            *(float4*)&a[0] = *(const float4*)&As[kk][tm];
            *(float4*)&a[4] = *(const float4*)&As[kk][tm + 4];
            unsigned long long b2v[4];
            float bl[8];
            *(float4*)&bl[0] = *(const float4*)&Bs[kk][tn];
            *(float4*)&bl[4] = *(const float4*)&Bs[kk][tn + 4];
            #pragma unroll
            for (int j = 0; j < 4; j++) b2v[j] = pack2(bl[2 * j], bl[2 * j + 1]);
            #pragma unroll
            for (int i = 0; i < 8; i++) {
                unsigned long long a2 = pack2(a[i], a[i]);
                #pragma unroll
                for (int j = 0; j < 4; j++) acc[i][j] = fma2(a2, b2v[j], acc[i][j]);
            }
        }
        __syncthreads();
    }

    // attention vectors for this block's 8 columns
    float aS[8], aD[8];
    #pragma unroll
    for (int j = 0; j < 8; j++) {
        aS[j] = a_src[bn + tn + j];
        aD[j] = a_dst[bn + tn + j];
    }
    #pragma unroll
    for (int i = 0; i < 8; i++) {
        int m = bm + tm + i;
        float o[8];
        #pragma unroll
        for (int j = 0; j < 4; j++) unpack2(acc[i][j], o[2 * j], o[2 * j + 1]);
        if (m < M) {
            float* dst = C + (size_t)m * N + bn + tn;
            *(float4*)dst = *(float4*)&o[0];
            *(float4*)(dst + 4) = *(float4*)&o[4];
        }
        float s = 0.f, dv = 0.f;
        #pragma unroll
        for (int j = 0; j < 8; j++) { s += o[j] * aS[j]; dv += o[j] * aD[j]; }
        #pragma unroll
        for (int o2 = 1; o2 < 8; o2 <<= 1) {
            s  += __shfl_xor_sync(0xFFFFFFFFu, s, o2);
            dv += __shfl_xor_sync(0xFFFFFFFFu, dv, o2);
        }
        if ((tid & 7) == 0 && m < M) {
            es[m * ESTRIDE + head] = s;
            ed[m * ESTRIDE + head] = dv;
        }
    }
}

// ---------------- layer-1 pull aggregation: warp per (node, head) ----------------
__global__ void agg1_kernel(const int* __restrict__ off, const int* __restrict__ csr,
                            const float* __restrict__ h,
                            const float* __restrict__ es, const float* __restrict__ ed,
                            const float* __restrict__ b1, float* __restrict__ out) {
    int gw = (blockIdx.x * blockDim.x + threadIdx.x) >> 5;
    int lane = threadIdx.x & 31;
    if (gw >= N_NODES * HEADS) return;
    int n = gw >> 2, head = gw & 3;
    int beg = off[n], end = off[n + 1];
    float edn = ed[n * HEADS + head];
    float accx = 0.f, accy = 0.f, zsum = 0.f;
    for (int base = beg; base < end; base += 32) {
        int m = min(32, end - base);
        int sl = 0; float pl = 0.f;
        if (base + lane < end) {
            sl = csr[base + lane];
            float l = es[sl * HEADS + head] + edn;
            l = l > 0.f ? l : 0.2f * l;
            pl = expf(l);
        }
        for (int j = 0; j < m; j++) {
            int s = __shfl_sync(0xFFFFFFFFu, sl, j);
            float p = __shfl_sync(0xFFFFFFFFu, pl, j);
            zsum += p;
            float2 v = *(const float2*)(h + (size_t)s * F1 + head * 64 + lane * 2);
            accx += p * v.x;
            accy += p * v.y;
        }
    }
    float inv = 1.f / zsum;
    int c = head * 64 + lane * 2;
    float o0 = accx * inv + b1[c];
    float o1 = accy * inv + b1[c + 1];
    o0 = o0 > 0.f ? o0 : expm1f(o0);
    o1 = o1 > 0.f ? o1 : expm1f(o1);
    float2 r; r.x = o0; r.y = o1;
    *(float2*)(out + (size_t)n * F1 + c) = r;
}

// ---------------- layer-2 pull aggregation: warp per node ----------------
__global__ void agg2_kernel(const int* __restrict__ off, const int* __restrict__ csr,
                            const float* __restrict__ h2,
                            const float* __restrict__ es, const float* __restrict__ ed,
                            const float* __restrict__ b2, float* __restrict__ out) {
    int n = (blockIdx.x * blockDim.x + threadIdx.x) >> 5;
    int lane = threadIdx.x & 31;
    if (n >= N_NODES) return;
    int beg = off[n], end = off[n + 1];
    float edn = ed[n];
    float accx = 0.f, accy = 0.f, zsum = 0.f;
    for (int base = beg; base < end; base += 32) {
        int m = min(32, end - base);
        int sl = 0; float pl = 0.f;
        if (base + lane < end) {
            sl = csr[base + lane];
            float l = es[sl] + edn;
            l = l > 0.f ? l : 0.2f * l;
            pl = expf(l);
        }
        for (int j = 0; j < m; j++) {
            int s = __shfl_sync(0xFFFFFFFFu, sl, j);
            float p = __shfl_sync(0xFFFFFFFFu, pl, j);
            zsum += p;
            float2 v = *(const float2*)(h2 + (size_t)s * OUT_C + lane * 2);
            accx += p * v.x;
            accy += p * v.y;
        }
    }
    float inv = 1.f / zsum;
    float2 r;
    r.x = accx * inv + b2[lane * 2];
    r.y = accy * inv + b2[lane * 2 + 1];
    *(float2*)(out + (size_t)n * OUT_C + lane * 2) = r;
}

extern "C" void kernel_launch(void* const* d_in, const int* in_sizes, int n_in,
                              void* d_out, int out_size) {
    const float* x    = (const float*)d_in[0];
    const int*   ei   = (const int*)d_in[1];
    const float* W1   = (const float*)d_in[2];
    const float* a1s  = (const float*)d_in[3];
    const float* a1d  = (const float*)d_in[4];
    const float* b1   = (const float*)d_in[5];
    const float* W2   = (const float*)d_in[6];
    const float* a2s  = (const float*)d_in[7];
    const float* a2d  = (const float*)d_in[8];
    const float* b2   = (const float*)d_in[9];
    float* out = (float*)d_out;

    float *h1, *out1, *h2, *e1s, *e1d, *e2s, *e2d;
    int *cnt, *off, *cursor, *csr;
    cudaGetSymbolAddress((void**)&h1,  g_h1);
    cudaGetSymbolAddress((void**)&out1, g_out1);
    cudaGetSymbolAddress((void**)&h2,  g_h2);
    cudaGetSymbolAddress((void**)&e1s, g_e1s);
    cudaGetSymbolAddress((void**)&e1d, g_e1d);
    cudaGetSymbolAddress((void**)&e2s, g_e2s);
    cudaGetSymbolAddress((void**)&e2d, g_e2d);
    cudaGetSymbolAddress((void**)&cnt, g_cnt);
    cudaGetSymbolAddress((void**)&off, g_off);
    cudaGetSymbolAddress((void**)&cursor, g_cursor);
    cudaGetSymbolAddress((void**)&csr, g_csr);

    // ---- CSR build ----
    initcnt_kernel<<<(N_NODES + 255) / 256, 256>>>(cnt);
    count_kernel<<<(E_EDGES / 4 + 255) / 256, 256>>>(ei, cnt);
    scan_kernel<<<1, 1024>>>(cnt, off, cursor, csr);
    fill_kernel<<<(E_EDGES / 4 + 255) / 256, 256>>>(ei, cursor, csr);

    // ---- Layer 1 (GEMM + fused attention dots) ----
    {
        dim3 grid(F1 / 64, (N_NODES + 127) / 128);
        sgemm2_kernel<HEADS><<<grid, 128>>>(x, W1, h1, N_NODES, IN_C,
                                            a1s, a1d, e1s, e1d);
    }
    agg1_kernel<<<(N_NODES * HEADS * 32 + 255) / 256, 256>>>(off, csr, h1, e1s, e1d, b1, out1);

    // ---- Layer 2 ----
    {
        dim3 grid(OUT_C / 64, (N_NODES + 127) / 128);
        sgemm2_kernel<1><<<grid, 128>>>(out1, W2, h2, N_NODES, F1,
                                        a2s, a2d, e2s, e2d);
    }
    agg2_kernel<<<(N_NODES * 32 + 255) / 256, 256>>>(off, csr, h2, e2s, e2d, b2, out);
}

// round 6
// speedup vs baseline: 1.3406x; 1.0260x over previous
#include <cuda_runtime.h>

#define N_NODES 20000
#define E_EDGES 320000
#define E_TOT   (E_EDGES + N_NODES)
#define IN_C    256
#define HID     64
#define HEADS   4
#define OUT_C   64
#define F1      (HEADS * HID)         // 256

// ---------------- scratch (device globals, no allocs) ----------------
__device__ float g_h1[(size_t)N_NODES * F1];
__device__ float g_out1[(size_t)N_NODES * F1];
__device__ float g_h2[(size_t)N_NODES * OUT_C];
__device__ float g_e1s[N_NODES * HEADS];
__device__ float g_e1d[N_NODES * HEADS];
__device__ float g_e2s[N_NODES];
__device__ float g_e2d[N_NODES];
__device__ int   g_cnt[N_NODES];
__device__ int   g_off[N_NODES + 1];
__device__ int   g_rank[E_EDGES];
__device__ int   g_csr[E_TOT];

// ---------------- packed f32x2 helpers ----------------
__device__ __forceinline__ unsigned long long pack2(float lo, float hi) {
    unsigned long long r;
    asm("mov.b64 %0, {%1, %2};" : "=l"(r) : "f"(lo), "f"(hi));
    return r;
}
__device__ __forceinline__ void unpack2(unsigned long long v, float& lo, float& hi) {
    asm("mov.b64 {%0, %1}, %2;" : "=f"(lo), "=f"(hi) : "l"(v));
}
__device__ __forceinline__ unsigned long long fma2(unsigned long long a,
                                                   unsigned long long b,
                                                   unsigned long long c) {
    unsigned long long d;
    asm("fma.rn.f32x2 %0, %1, %2, %3;" : "=l"(d) : "l"(a), "l"(b), "l"(c));
    return d;
}

// ================= CSR build =================
__global__ void initcnt_kernel(int* __restrict__ cnt) {
    int i = blockIdx.x * blockDim.x + threadIdx.x;
    if (i < N_NODES) cnt[i] = 0;
}
// count + record per-edge rank (atomic return), 4 edges/thread
__global__ void count_kernel(const int* __restrict__ ei, int* __restrict__ cnt,
                             int* __restrict__ rank) {
    int e = (blockIdx.x * blockDim.x + threadIdx.x) * 4;
    if (e >= E_EDGES) return;
    int4 d4 = *(const int4*)(ei + E_EDGES + e);
    int4 r4;
    r4.x = atomicAdd(&cnt[d4.x], 1);
    r4.y = atomicAdd(&cnt[d4.y], 1);
    r4.z = atomicAdd(&cnt[d4.z], 1);
    r4.w = atomicAdd(&cnt[d4.w], 1);
    *(int4*)(rank + e) = r4;
}
// single-block scan of (cnt+1); places self-loops at slot 0 of each segment
__global__ void __launch_bounds__(1024) scan_kernel(const int* __restrict__ cnt,
                                                    int* __restrict__ off,
                                                    int* __restrict__ csr) {
    __shared__ int wsum[32];
    const int CH = (N_NODES + 1023) / 1024;   // 20
    int tid = threadIdx.x;
    int lane = tid & 31, warp = tid >> 5;
    int base = tid * CH;
    int local[CH];
    int sum = 0;
    #pragma unroll
    for (int i = 0; i < CH; i++) {
        int idx = base + i;
        int v = idx < N_NODES ? (cnt[idx] + 1) : 0;   // +1 self-loop
        local[i] = sum;
        sum += v;
    }
    int inc = sum;
    #pragma unroll
    for (int o = 1; o < 32; o <<= 1) {
        int t = __shfl_up_sync(0xFFFFFFFFu, inc, o);
        if (lane >= o) inc += t;
    }
    if (lane == 31) wsum[warp] = inc;
    __syncthreads();
    if (warp == 0) {
        int w = wsum[lane];
        #pragma unroll
        for (int o = 1; o < 32; o <<= 1) {
            int t = __shfl_up_sync(0xFFFFFFFFu, w, o);
            if (lane >= o) w += t;
        }
        wsum[lane] = w;
    }
    __syncthreads();
    int prev = inc - sum + (warp ? wsum[warp - 1] : 0);
    #pragma unroll
    for (int i = 0; i < CH; i++) {
        int idx = base + i;
        if (idx < N_NODES) {
            int v = prev + local[i];
            off[idx] = v;
            csr[v] = idx;   // self-loop at slot 0
        }
    }
    if (tid == 1023) off[N_NODES] = prev + sum;
}
// atomic-free fill using precomputed ranks
__global__ void fill_kernel(const int* __restrict__ ei, const int* __restrict__ off,
                            const int* __restrict__ rank, int* __restrict__ csr) {
    int e = (blockIdx.x * blockDim.x + threadIdx.x) * 4;
    if (e >= E_EDGES) return;
    int4 s4 = *(const int4*)(ei + e);
    int4 d4 = *(const int4*)(ei + E_EDGES + e);
    int4 r4 = *(const int4*)(rank + e);
    csr[off[d4.x] + 1 + r4.x] = s4.x;
    csr[off[d4.y] + 1 + r4.y] = s4.y;
    csr[off[d4.z] + 1 + r4.z] = s4.z;
    csr[off[d4.w] + 1 + r4.w] = s4.w;
}

// ---------- packed-f32x2 SGEMM with fused attention-dot epilogue ----------
template<int ESTRIDE>
__global__ void __launch_bounds__(128)
sgemm2_kernel(const float* __restrict__ A, const float* __restrict__ B,
              float* __restrict__ C, int M, int K,
              const float* __restrict__ a_src, const float* __restrict__ a_dst,
              float* __restrict__ es, float* __restrict__ ed) {
    const int N = ESTRIDE * 64;
    __shared__ float As[16][132];
    __shared__ float Bs[16][68];
    const int bm = blockIdx.y * 128;
    const int bn = blockIdx.x * 64;
    const int head = bn >> 6;
    const int tid = threadIdx.x;
    const int tm = (tid >> 3) * 8;
    const int tn = (tid & 7) * 8;

    unsigned long long acc[8][4];
    #pragma unroll
    for (int i = 0; i < 8; i++)
        #pragma unroll
        for (int j = 0; j < 4; j++) acc[i][j] = 0ull;

    for (int k0 = 0; k0 < K; k0 += 16) {
        {
            int r = tid;
            int row = bm + r;
            #pragma unroll
            for (int cc = 0; cc < 4; cc++) {
                int c = cc * 4;
                float4 v = make_float4(0.f, 0.f, 0.f, 0.f);
                if (row < M) v = *(const float4*)(A + (size_t)row * K + k0 + c);
                As[c + 0][r] = v.x; As[c + 1][r] = v.y;
                As[c + 2][r] = v.z; As[c + 3][r] = v.w;
            }
        }
        {
            int r = tid >> 3;
            int c = (tid & 7) * 8;
            const float* src = B + (size_t)(k0 + r) * N + bn + c;
            *(float4*)&Bs[r][c] = *(const float4*)src;
            *(float4*)&Bs[r][c + 4] = *(const float4*)(src + 4);
        }
        __syncthreads();
        #pragma unroll
        for (int kk = 0; kk < 16; kk++) {
            float a[8];
            *(float4*)&a[0] = *(const float4*)&As[kk][tm];
            *(float4*)&a[4] = *(const float4*)&As[kk][tm + 4];
            unsigned long long b2v[4];
            float bl[8];
            *(float4*)&bl[0] = *(const float4*)&Bs[kk][tn];
            *(float4*)&bl[4] = *(const float4*)&Bs[kk][tn + 4];
            #pragma unroll
            for (int j = 0; j < 4; j++) b2v[j] = pack2(bl[2 * j], bl[2 * j + 1]);
            #pragma unroll
            for (int i = 0; i < 8; i++) {
                unsigned long long a2 = pack2(a[i], a[i]);
                #pragma unroll
                for (int j = 0; j < 4; j++) acc[i][j] = fma2(a2, b2v[j], acc[i][j]);
            }
        }
        __syncthreads();
    }

    float aS[8], aD[8];
    #pragma unroll
    for (int j = 0; j < 8; j++) {
        aS[j] = a_src[bn + tn + j];
        aD[j] = a_dst[bn + tn + j];
    }
    #pragma unroll
    for (int i = 0; i < 8; i++) {
        int m = bm + tm + i;
        float o[8];
        #pragma unroll
        for (int j = 0; j < 4; j++) unpack2(acc[i][j], o[2 * j], o[2 * j + 1]);
        if (m < M) {
            float* dst = C + (size_t)m * N + bn + tn;
            *(float4*)dst = *(float4*)&o[0];
            *(float4*)(dst + 4) = *(float4*)&o[4];
        }
        float s = 0.f, dv = 0.f;
        #pragma unroll
        for (int j = 0; j < 8; j++) { s += o[j] * aS[j]; dv += o[j] * aD[j]; }
        #pragma unroll
        for (int o2 = 1; o2 < 8; o2 <<= 1) {
            s  += __shfl_xor_sync(0xFFFFFFFFu, s, o2);
            dv += __shfl_xor_sync(0xFFFFFFFFu, dv, o2);
        }
        if ((tid & 7) == 0 && m < M) {
            es[m * ESTRIDE + head] = s;
            ed[m * ESTRIDE + head] = dv;
        }
    }
}

// ---------------- layer-1 pull aggregation: warp per (node, head) ----------------
__global__ void agg1_kernel(const int* __restrict__ off, const int* __restrict__ csr,
                            const float* __restrict__ h,
                            const float* __restrict__ es, const float* __restrict__ ed,
                            const float* __restrict__ b1, float* __restrict__ out) {
    int gw = (blockIdx.x * blockDim.x + threadIdx.x) >> 5;
    int lane = threadIdx.x & 31;
    if (gw >= N_NODES * HEADS) return;
    int n = gw >> 2, head = gw & 3;
    int beg = off[n], end = off[n + 1];
    float edn = ed[n * HEADS + head];
    float accx = 0.f, accy = 0.f, zsum = 0.f;
    for (int base = beg; base < end; base += 32) {
        int m = min(32, end - base);
        int sl = 0; float pl = 0.f;
        if (base + lane < end) {
            sl = csr[base + lane];
            float l = es[sl * HEADS + head] + edn;
            l = l > 0.f ? l : 0.2f * l;
            pl = expf(l);
        }
        int j = 0;
        for (; j + 2 <= m; j += 2) {
            int s0 = __shfl_sync(0xFFFFFFFFu, sl, j);
            int s1 = __shfl_sync(0xFFFFFFFFu, sl, j + 1);
            float p0 = __shfl_sync(0xFFFFFFFFu, pl, j);
            float p1 = __shfl_sync(0xFFFFFFFFu, pl, j + 1);
            float2 v0 = *(const float2*)(h + (size_t)s0 * F1 + head * 64 + lane * 2);
            float2 v1 = *(const float2*)(h + (size_t)s1 * F1 + head * 64 + lane * 2);
            zsum += p0 + p1;
            accx += p0 * v0.x + p1 * v1.x;
            accy += p0 * v0.y + p1 * v1.y;
        }
        if (j < m) {
            int s0 = __shfl_sync(0xFFFFFFFFu, sl, j);
            float p0 = __shfl_sync(0xFFFFFFFFu, pl, j);
            float2 v0 = *(const float2*)(h + (size_t)s0 * F1 + head * 64 + lane * 2);
            zsum += p0;
            accx += p0 * v0.x;
            accy += p0 * v0.y;
        }
    }
    float inv = 1.f / zsum;
    int c = head * 64 + lane * 2;
    float o0 = accx * inv + b1[c];
    float o1 = accy * inv + b1[c + 1];
    o0 = o0 > 0.f ? o0 : expm1f(o0);
    o1 = o1 > 0.f ? o1 : expm1f(o1);
    float2 r; r.x = o0; r.y = o1;
    *(float2*)(out + (size_t)n * F1 + c) = r;
}

// ---------------- layer-2 pull aggregation: warp per node ----------------
__global__ void agg2_kernel(const int* __restrict__ off, const int* __restrict__ csr,
                            const float* __restrict__ h2,
                            const float* __restrict__ es, const float* __restrict__ ed,
                            const float* __restrict__ b2, float* __restrict__ out) {
    int n = (blockIdx.x * blockDim.x + threadIdx.x) >> 5;
    int lane = threadIdx.x & 31;
    if (n >= N_NODES) return;
    int beg = off[n], end = off[n + 1];
    float edn = ed[n];
    float accx = 0.f, accy = 0.f, zsum = 0.f;
    for (int base = beg; base < end; base += 32) {
        int m = min(32, end - base);
        int sl = 0; float pl = 0.f;
        if (base + lane < end) {
            sl = csr[base + lane];
            float l = es[sl] + edn;
            l = l > 0.f ? l : 0.2f * l;
            pl = expf(l);
        }
        int j = 0;
        for (; j + 2 <= m; j += 2) {
            int s0 = __shfl_sync(0xFFFFFFFFu, sl, j);
            int s1 = __shfl_sync(0xFFFFFFFFu, sl, j + 1);
            float p0 = __shfl_sync(0xFFFFFFFFu, pl, j);
            float p1 = __shfl_sync(0xFFFFFFFFu, pl, j + 1);
            float2 v0 = *(const float2*)(h2 + (size_t)s0 * OUT_C + lane * 2);
            float2 v1 = *(const float2*)(h2 + (size_t)s1 * OUT_C + lane * 2);
            zsum += p0 + p1;
            accx += p0 * v0.x + p1 * v1.x;
            accy += p0 * v0.y + p1 * v1.y;
        }
        if (j < m) {
            int s0 = __shfl_sync(0xFFFFFFFFu, sl, j);
            float p0 = __shfl_sync(0xFFFFFFFFu, pl, j);
            float2 v0 = *(const float2*)(h2 + (size_t)s0 * OUT_C + lane * 2);
            zsum += p0;
            accx += p0 * v0.x;
            accy += p0 * v0.y;
        }
    }
    float inv = 1.f / zsum;
    float2 r;
    r.x = accx * inv + b2[lane * 2];
    r.y = accy * inv + b2[lane * 2 + 1];
    *(float2*)(out + (size_t)n * OUT_C + lane * 2) = r;
}

extern "C" void kernel_launch(void* const* d_in, const int* in_sizes, int n_in,
                              void* d_out, int out_size) {
    const float* x    = (const float*)d_in[0];
    const int*   ei   = (const int*)d_in[1];
    const float* W1   = (const float*)d_in[2];
    const float* a1s  = (const float*)d_in[3];
    const float* a1d  = (const float*)d_in[4];
    const float* b1   = (const float*)d_in[5];
    const float* W2   = (const float*)d_in[6];
    const float* a2s  = (const float*)d_in[7];
    const float* a2d  = (const float*)d_in[8];
    const float* b2   = (const float*)d_in[9];
    float* out = (float*)d_out;

    float *h1, *out1, *h2, *e1s, *e1d, *e2s, *e2d;
    int *cnt, *off, *rank, *csr;
    cudaGetSymbolAddress((void**)&h1,  g_h1);
    cudaGetSymbolAddress((void**)&out1, g_out1);
    cudaGetSymbolAddress((void**)&h2,  g_h2);
    cudaGetSymbolAddress((void**)&e1s, g_e1s);
    cudaGetSymbolAddress((void**)&e1d, g_e1d);
    cudaGetSymbolAddress((void**)&e2s, g_e2s);
    cudaGetSymbolAddress((void**)&e2d, g_e2d);
    cudaGetSymbolAddress((void**)&cnt, g_cnt);
    cudaGetSymbolAddress((void**)&off, g_off);
    cudaGetSymbolAddress((void**)&rank, g_rank);
    cudaGetSymbolAddress((void**)&csr, g_csr);

    // ---- CSR build (launch order puts sgemm1 at index 3 for ncu) ----
    initcnt_kernel<<<(N_NODES + 255) / 256, 256>>>(cnt);                       // 0
    count_kernel<<<(E_EDGES / 4 + 255) / 256, 256>>>(ei, cnt, rank);           // 1
    scan_kernel<<<1, 1024>>>(cnt, off, csr);                                   // 2

    // ---- Layer 1 GEMM (+ fused attention dots) ----
    {
        dim3 grid(F1 / 64, (N_NODES + 127) / 128);
        sgemm2_kernel<HEADS><<<grid, 128>>>(x, W1, h1, N_NODES, IN_C,          // 3
                                            a1s, a1d, e1s, e1d);
    }
    fill_kernel<<<(E_EDGES / 4 + 255) / 256, 256>>>(ei, off, rank, csr);       // 4
    agg1_kernel<<<(N_NODES * HEADS * 32 + 255) / 256, 256>>>(off, csr, h1,     // 5
                                                             e1s, e1d, b1, out1);

    // ---- Layer 2 ----
    {
        dim3 grid(OUT_C / 64, (N_NODES + 127) / 128);
        sgemm2_kernel<1><<<grid, 128>>>(out1, W2, h2, N_NODES, F1,             // 6
                                        a2s, a2d, e2s, e2d);
    }
    agg2_kernel<<<(N_NODES * 32 + 255) / 256, 256>>>(off, csr, h2,             // 7
                                                     e2s, e2d, b2, out);
}

// round 7
// speedup vs baseline: 1.3454x; 1.0036x over previous
#include <cuda_runtime.h>

#define N_NODES 20000
#define E_EDGES 320000
#define E_TOT   (E_EDGES + N_NODES)
#define IN_C    256
#define HID     64
#define HEADS   4
#define OUT_C   64
#define F1      (HEADS * HID)         // 256

// ---------------- scratch (device globals, no allocs) ----------------
__device__ float g_h1[(size_t)N_NODES * F1];
__device__ float g_out1[(size_t)N_NODES * F1];
__device__ float g_h2[(size_t)N_NODES * OUT_C];
__device__ float g_e1s[N_NODES * HEADS];
__device__ float g_e1d[N_NODES * HEADS];
__device__ float g_e2s[N_NODES];
__device__ float g_e2d[N_NODES];
__device__ int   g_cnt[N_NODES];
__device__ int   g_off[N_NODES + 1];
__device__ int   g_rank[E_EDGES];
__device__ int   g_csr[E_TOT];

// ---------------- packed f32x2 helpers ----------------
__device__ __forceinline__ unsigned long long pack2(float lo, float hi) {
    unsigned long long r;
    asm("mov.b64 %0, {%1, %2};" : "=l"(r) : "f"(lo), "f"(hi));
    return r;
}
__device__ __forceinline__ void unpack2(unsigned long long v, float& lo, float& hi) {
    asm("mov.b64 {%0, %1}, %2;" : "=f"(lo), "=f"(hi) : "l"(v));
}
__device__ __forceinline__ unsigned long long fma2(unsigned long long a,
                                                   unsigned long long b,
                                                   unsigned long long c) {
    unsigned long long d;
    asm("fma.rn.f32x2 %0, %1, %2, %3;" : "=l"(d) : "l"(a), "l"(b), "l"(c));
    return d;
}

// ================= CSR build =================
__global__ void initcnt_kernel(int* __restrict__ cnt) {
    int i = blockIdx.x * blockDim.x + threadIdx.x;
    if (i < N_NODES) cnt[i] = 0;
}
__global__ void count_kernel(const int* __restrict__ ei, int* __restrict__ cnt,
                             int* __restrict__ rank) {
    int e = (blockIdx.x * blockDim.x + threadIdx.x) * 4;
    if (e >= E_EDGES) return;
    int4 d4 = *(const int4*)(ei + E_EDGES + e);
    int4 r4;
    r4.x = atomicAdd(&cnt[d4.x], 1);
    r4.y = atomicAdd(&cnt[d4.y], 1);
    r4.z = atomicAdd(&cnt[d4.z], 1);
    r4.w = atomicAdd(&cnt[d4.w], 1);
    *(int4*)(rank + e) = r4;
}
__global__ void __launch_bounds__(1024) scan_kernel(const int* __restrict__ cnt,
                                                    int* __restrict__ off,
                                                    int* __restrict__ csr) {
    __shared__ int wsum[32];
    const int CH = (N_NODES + 1023) / 1024;   // 20
    int tid = threadIdx.x;
    int lane = tid & 31, warp = tid >> 5;
    int base = tid * CH;
    int local[CH];
    int sum = 0;
    #pragma unroll
    for (int i = 0; i < CH; i++) {
        int idx = base + i;
        int v = idx < N_NODES ? (cnt[idx] + 1) : 0;   // +1 self-loop
        local[i] = sum;
        sum += v;
    }
    int inc = sum;
    #pragma unroll
    for (int o = 1; o < 32; o <<= 1) {
        int t = __shfl_up_sync(0xFFFFFFFFu, inc, o);
        if (lane >= o) inc += t;
    }
    if (lane == 31) wsum[warp] = inc;
    __syncthreads();
    if (warp == 0) {
        int w = wsum[lane];
        #pragma unroll
        for (int o = 1; o < 32; o <<= 1) {
            int t = __shfl_up_sync(0xFFFFFFFFu, w, o);
            if (lane >= o) w += t;
        }
        wsum[lane] = w;
    }
    __syncthreads();
    int prev = inc - sum + (warp ? wsum[warp - 1] : 0);
    #pragma unroll
    for (int i = 0; i < CH; i++) {
        int idx = base + i;
        if (idx < N_NODES) {
            int v = prev + local[i];
            off[idx] = v;
            csr[v] = idx;   // self-loop at slot 0
        }
    }
    if (tid == 1023) off[N_NODES] = prev + sum;
}
__global__ void fill_kernel(const int* __restrict__ ei, const int* __restrict__ off,
                            const int* __restrict__ rank, int* __restrict__ csr) {
    int e = (blockIdx.x * blockDim.x + threadIdx.x) * 4;
    if (e >= E_EDGES) return;
    int4 s4 = *(const int4*)(ei + e);
    int4 d4 = *(const int4*)(ei + E_EDGES + e);
    int4 r4 = *(const int4*)(rank + e);
    csr[off[d4.x] + 1 + r4.x] = s4.x;
    csr[off[d4.y] + 1 + r4.y] = s4.y;
    csr[off[d4.z] + 1 + r4.z] = s4.z;
    csr[off[d4.w] + 1 + r4.w] = s4.w;
}

// ---------- BIG GEMM (layer 1): BM=128, BN=128, BK=16, 256 threads, 8x8/thread ----------
// N fixed = 256 (F1). Fused attention-dot epilogue (ESTRIDE=HEADS).
__global__ void __launch_bounds__(256)
sgemm_big_kernel(const float* __restrict__ A, const float* __restrict__ B,
                 float* __restrict__ C, int M,
                 const float* __restrict__ a_src, const float* __restrict__ a_dst,
                 float* __restrict__ es, float* __restrict__ ed) {
    const int N = F1;      // 256
    const int K = IN_C;    // 256
    __shared__ float As[16][132];
    __shared__ float Bs[16][132];
    const int bm = blockIdx.y * 128;
    const int bn = blockIdx.x * 128;
    const int tid = threadIdx.x;
    const int tm = (tid >> 4) * 8;    // 16 m-groups
    const int tn = (tid & 15) * 8;    // 16 n-groups

    unsigned long long acc[8][4];
    #pragma unroll
    for (int i = 0; i < 8; i++)
        #pragma unroll
        for (int j = 0; j < 4; j++) acc[i][j] = 0ull;

    for (int k0 = 0; k0 < K; k0 += 16) {
        // A tile: 128 rows x 16 k; thread loads 8 k at one row, transposed store
        {
            int r = tid >> 1;
            int c = (tid & 1) * 8;
            int row = bm + r;
            float4 v0 = make_float4(0.f, 0.f, 0.f, 0.f), v1 = v0;
            if (row < M) {
                const float* src = A + (size_t)row * K + k0 + c;
                v0 = *(const float4*)src;
                v1 = *(const float4*)(src + 4);
            }
            As[c + 0][r] = v0.x; As[c + 1][r] = v0.y;
            As[c + 2][r] = v0.z; As[c + 3][r] = v0.w;
            As[c + 4][r] = v1.x; As[c + 5][r] = v1.y;
            As[c + 6][r] = v1.z; As[c + 7][r] = v1.w;
        }
        // B tile: 16 x 128; thread loads 8 contiguous cols
        {
            int r = tid >> 4;
            int c = (tid & 15) * 8;
            const float* src = B + (size_t)(k0 + r) * N + bn + c;
            *(float4*)&Bs[r][c] = *(const float4*)src;
            *(float4*)&Bs[r][c + 4] = *(const float4*)(src + 4);
        }
        __syncthreads();
        #pragma unroll
        for (int kk = 0; kk < 16; kk++) {
            float a[8];
            *(float4*)&a[0] = *(const float4*)&As[kk][tm];
            *(float4*)&a[4] = *(const float4*)&As[kk][tm + 4];
            float bl[8];
            *(float4*)&bl[0] = *(const float4*)&Bs[kk][tn];
            *(float4*)&bl[4] = *(const float4*)&Bs[kk][tn + 4];
            unsigned long long b2v[4];
            #pragma unroll
            for (int j = 0; j < 4; j++) b2v[j] = pack2(bl[2 * j], bl[2 * j + 1]);
            #pragma unroll
            for (int i = 0; i < 8; i++) {
                unsigned long long a2 = pack2(a[i], a[i]);
                #pragma unroll
                for (int j = 0; j < 4; j++) acc[i][j] = fma2(a2, b2v[j], acc[i][j]);
            }
        }
        __syncthreads();
    }

    // epilogue: store C + fused attention dots
    // head for this thread's 8 cols: bn/64 + (tid&15)/8
    const int head = (bn >> 6) + ((tid & 15) >> 3);
    float aS[8], aD[8];
    #pragma unroll
    for (int j = 0; j < 8; j++) {
        aS[j] = a_src[bn + tn + j];
        aD[j] = a_dst[bn + tn + j];
    }
    #pragma unroll
    for (int i = 0; i < 8; i++) {
        int m = bm + tm + i;
        float o[8];
        #pragma unroll
        for (int j = 0; j < 4; j++) unpack2(acc[i][j], o[2 * j], o[2 * j + 1]);
        if (m < M) {
            float* dst = C + (size_t)m * N + bn + tn;
            *(float4*)dst = *(float4*)&o[0];
            *(float4*)(dst + 4) = *(float4*)&o[4];
        }
        float s = 0.f, dv = 0.f;
        #pragma unroll
        for (int j = 0; j < 8; j++) { s += o[j] * aS[j]; dv += o[j] * aD[j]; }
        // reduce across the 8 threads covering one head (lanes differ in bits 0..2)
        #pragma unroll
        for (int o2 = 1; o2 < 8; o2 <<= 1) {
            s  += __shfl_xor_sync(0xFFFFFFFFu, s, o2);
            dv += __shfl_xor_sync(0xFFFFFFFFu, dv, o2);
        }
        if ((tid & 7) == 0 && m < M) {
            es[m * HEADS + head] = s;
            ed[m * HEADS + head] = dv;
        }
    }
}

// ---------- layer-2 GEMM (proven 128-thread version, BN=64, ESTRIDE=1) ----------
__global__ void __launch_bounds__(128)
sgemm2_kernel(const float* __restrict__ A, const float* __restrict__ B,
              float* __restrict__ C, int M, int K,
              const float* __restrict__ a_src, const float* __restrict__ a_dst,
              float* __restrict__ es, float* __restrict__ ed) {
    const int N = 64;
    __shared__ float As[16][132];
    __shared__ float Bs[16][68];
    const int bm = blockIdx.y * 128;
    const int bn = 0;
    const int tid = threadIdx.x;
    const int tm = (tid >> 3) * 8;
    const int tn = (tid & 7) * 8;

    unsigned long long acc[8][4];
    #pragma unroll
    for (int i = 0; i < 8; i++)
        #pragma unroll
        for (int j = 0; j < 4; j++) acc[i][j] = 0ull;

    for (int k0 = 0; k0 < K; k0 += 16) {
        {
            int r = tid;
            int row = bm + r;
            #pragma unroll
            for (int cc = 0; cc < 4; cc++) {
                int c = cc * 4;
                float4 v = make_float4(0.f, 0.f, 0.f, 0.f);
                if (row < M) v = *(const float4*)(A + (size_t)row * K + k0 + c);
                As[c + 0][r] = v.x; As[c + 1][r] = v.y;
                As[c + 2][r] = v.z; As[c + 3][r] = v.w;
            }
        }
        {
            int r = tid >> 3;
            int c = (tid & 7) * 8;
            const float* src = B + (size_t)(k0 + r) * N + bn + c;
            *(float4*)&Bs[r][c] = *(const float4*)src;
            *(float4*)&Bs[r][c + 4] = *(const float4*)(src + 4);
        }
        __syncthreads();
        #pragma unroll
        for (int kk = 0; kk < 16; kk++) {
            float a[8];
            *(float4*)&a[0] = *(const float4*)&As[kk][tm];
            *(float4*)&a[4] = *(const float4*)&As[kk][tm + 4];
            unsigned long long b2v[4];
            float bl[8];
            *(float4*)&bl[0] = *(const float4*)&Bs[kk][tn];
            *(float4*)&bl[4] = *(const float4*)&Bs[kk][tn + 4];
            #pragma unroll
            for (int j = 0; j < 4; j++) b2v[j] = pack2(bl[2 * j], bl[2 * j + 1]);
            #pragma unroll
            for (int i = 0; i < 8; i++) {
                unsigned long long a2 = pack2(a[i], a[i]);
                #pragma unroll
                for (int j = 0; j < 4; j++) acc[i][j] = fma2(a2, b2v[j], acc[i][j]);
            }
        }
        __syncthreads();
    }

    float aS[8], aD[8];
    #pragma unroll
    for (int j = 0; j < 8; j++) {
        aS[j] = a_src[tn + j];
        aD[j] = a_dst[tn + j];
    }
    #pragma unroll
    for (int i = 0; i < 8; i++) {
        int m = bm + tm + i;
        float o[8];
        #pragma unroll
        for (int j = 0; j < 4; j++) unpack2(acc[i][j], o[2 * j], o[2 * j + 1]);
        if (m < M) {
            float* dst = C + (size_t)m * N + tn;
            *(float4*)dst = *(float4*)&o[0];
            *(float4*)(dst + 4) = *(float4*)&o[4];
        }
        float s = 0.f, dv = 0.f;
        #pragma unroll
        for (int j = 0; j < 8; j++) { s += o[j] * aS[j]; dv += o[j] * aD[j]; }
        #pragma unroll
        for (int o2 = 1; o2 < 8; o2 <<= 1) {
            s  += __shfl_xor_sync(0xFFFFFFFFu, s, o2);
            dv += __shfl_xor_sync(0xFFFFFFFFu, dv, o2);
        }
        if ((tid & 7) == 0 && m < M) {
            es[m] = s;
            ed[m] = dv;
        }
    }
}

// ---------------- layer-1 pull aggregation: warp per (node, head) ----------------
__global__ void agg1_kernel(const int* __restrict__ off, const int* __restrict__ csr,
                            const float* __restrict__ h,
                            const float* __restrict__ es, const float* __restrict__ ed,
                            const float* __restrict__ b1, float* __restrict__ out) {
    int gw = (blockIdx.x * blockDim.x + threadIdx.x) >> 5;
    int lane = threadIdx.x & 31;
    if (gw >= N_NODES * HEADS) return;
    int n = gw >> 2, head = gw & 3;
    int beg = off[n], end = off[n + 1];
    float edn = ed[n * HEADS + head];
    float accx = 0.f, accy = 0.f, zsum = 0.f;
    for (int base = beg; base < end; base += 32) {
        int m = min(32, end - base);
        int sl = 0; float pl = 0.f;
        if (base + lane < end) {
            sl = csr[base + lane];
            float l = es[sl * HEADS + head] + edn;
            l = l > 0.f ? l : 0.2f * l;
            pl = expf(l);
        }
        int j = 0;
        for (; j + 2 <= m; j += 2) {
            int s0 = __shfl_sync(0xFFFFFFFFu, sl, j);
            int s1 = __shfl_sync(0xFFFFFFFFu, sl, j + 1);
            float p0 = __shfl_sync(0xFFFFFFFFu, pl, j);
            float p1 = __shfl_sync(0xFFFFFFFFu, pl, j + 1);
            float2 v0 = *(const float2*)(h + (size_t)s0 * F1 + head * 64 + lane * 2);
            float2 v1 = *(const float2*)(h + (size_t)s1 * F1 + head * 64 + lane * 2);
            zsum += p0 + p1;
            accx += p0 * v0.x + p1 * v1.x;
            accy += p0 * v0.y + p1 * v1.y;
        }
        if (j < m) {
            int s0 = __shfl_sync(0xFFFFFFFFu, sl, j);
            float p0 = __shfl_sync(0xFFFFFFFFu, pl, j);
            float2 v0 = *(const float2*)(h + (size_t)s0 * F1 + head * 64 + lane * 2);
            zsum += p0;
            accx += p0 * v0.x;
            accy += p0 * v0.y;
        }
    }
    float inv = 1.f / zsum;
    int c = head * 64 + lane * 2;
    float o0 = accx * inv + b1[c];
    float o1 = accy * inv + b1[c + 1];
    o0 = o0 > 0.f ? o0 : expm1f(o0);
    o1 = o1 > 0.f ? o1 : expm1f(o1);
    float2 r; r.x = o0; r.y = o1;
    *(float2*)(out + (size_t)n * F1 + c) = r;
}

// ---------------- layer-2 pull aggregation: warp per node ----------------
__global__ void agg2_kernel(const int* __restrict__ off, const int* __restrict__ csr,
                            const float* __restrict__ h2,
                            const float* __restrict__ es, const float* __restrict__ ed,
                            const float* __restrict__ b2, float* __restrict__ out) {
    int n = (blockIdx.x * blockDim.x + threadIdx.x) >> 5;
    int lane = threadIdx.x & 31;
    if (n >= N_NODES) return;
    int beg = off[n], end = off[n + 1];
    float edn = ed[n];
    float accx = 0.f, accy = 0.f, zsum = 0.f;
    for (int base = beg; base < end; base += 32) {
        int m = min(32, end - base);
        int sl = 0; float pl = 0.f;
        if (base + lane < end) {
            sl = csr[base + lane];
            float l = es[sl] + edn;
            l = l > 0.f ? l : 0.2f * l;
            pl = expf(l);
        }
        int j = 0;
        for (; j + 2 <= m; j += 2) {
            int s0 = __shfl_sync(0xFFFFFFFFu, sl, j);
            int s1 = __shfl_sync(0xFFFFFFFFu, sl, j + 1);
            float p0 = __shfl_sync(0xFFFFFFFFu, pl, j);
            float p1 = __shfl_sync(0xFFFFFFFFu, pl, j + 1);
            float2 v0 = *(const float2*)(h2 + (size_t)s0 * OUT_C + lane * 2);
            float2 v1 = *(const float2*)(h2 + (size_t)s1 * OUT_C + lane * 2);
            zsum += p0 + p1;
            accx += p0 * v0.x + p1 * v1.x;
            accy += p0 * v0.y + p1 * v1.y;
        }
        if (j < m) {
            int s0 = __shfl_sync(0xFFFFFFFFu, sl, j);
            float p0 = __shfl_sync(0xFFFFFFFFu, pl, j);
            float2 v0 = *(const float2*)(h2 + (size_t)s0 * OUT_C + lane * 2);
            zsum += p0;
            accx += p0 * v0.x;
            accy += p0 * v0.y;
        }
    }
    float inv = 1.f / zsum;
    float2 r;
    r.x = accx * inv + b2[lane * 2];
    r.y = accy * inv + b2[lane * 2 + 1];
    *(float2*)(out + (size_t)n * OUT_C + lane * 2) = r;
}

extern "C" void kernel_launch(void* const* d_in, const int* in_sizes, int n_in,
                              void* d_out, int out_size) {
    const float* x    = (const float*)d_in[0];
    const int*   ei   = (const int*)d_in[1];
    const float* W1   = (const float*)d_in[2];
    const float* a1s  = (const float*)d_in[3];
    const float* a1d  = (const float*)d_in[4];
    const float* b1   = (const float*)d_in[5];
    const float* W2   = (const float*)d_in[6];
    const float* a2s  = (const float*)d_in[7];
    const float* a2d  = (const float*)d_in[8];
    const float* b2   = (const float*)d_in[9];
    float* out = (float*)d_out;

    float *h1, *out1, *h2, *e1s, *e1d, *e2s, *e2d;
    int *cnt, *off, *rank, *csr;
    cudaGetSymbolAddress((void**)&h1,  g_h1);
    cudaGetSymbolAddress((void**)&out1, g_out1);
    cudaGetSymbolAddress((void**)&h2,  g_h2);
    cudaGetSymbolAddress((void**)&e1s, g_e1s);
    cudaGetSymbolAddress((void**)&e1d, g_e1d);
    cudaGetSymbolAddress((void**)&e2s, g_e2s);
    cudaGetSymbolAddress((void**)&e2d, g_e2d);
    cudaGetSymbolAddress((void**)&cnt, g_cnt);
    cudaGetSymbolAddress((void**)&off, g_off);
    cudaGetSymbolAddress((void**)&rank, g_rank);
    cudaGetSymbolAddress((void**)&csr, g_csr);

    // ---- CSR build (sgemm1 stays at launch index 3 for ncu) ----
    initcnt_kernel<<<(N_NODES + 255) / 256, 256>>>(cnt);                       // 0
    count_kernel<<<(E_EDGES / 4 + 255) / 256, 256>>>(ei, cnt, rank);           // 1
    scan_kernel<<<1, 1024>>>(cnt, off, csr);                                   // 2

    // ---- Layer 1 GEMM (+ fused attention dots) ----
    {
        dim3 grid(F1 / 128, (N_NODES + 127) / 128);
        sgemm_big_kernel<<<grid, 256>>>(x, W1, h1, N_NODES,                    // 3
                                        a1s, a1d, e1s, e1d);
    }
    fill_kernel<<<(E_EDGES / 4 + 255) / 256, 256>>>(ei, off, rank, csr);       // 4
    agg1_kernel<<<(N_NODES * HEADS * 32 + 255) / 256, 256>>>(off, csr, h1,     // 5
                                                             e1s, e1d, b1, out1);

    // ---- Layer 2 ----
    {
        dim3 grid(1, (N_NODES + 127) / 128);
        sgemm2_kernel<<<grid, 128>>>(out1, W2, h2, N_NODES, F1,                // 6
                                     a2s, a2d, e2s, e2d);
    }
    agg2_kernel<<<(N_NODES * 32 + 255) / 256, 256>>>(off, csr, h2,             // 7
                                                     e2s, e2d, b2, out);
}

// round 9
// speedup vs baseline: 1.5590x; 1.1587x over previous
#include <cuda_runtime.h>
#include <cuda_bf16.h>
#include <cstdint>

#define N_NODES 20000
#define E_EDGES 320000
#define E_TOT   (E_EDGES + N_NODES)
#define IN_C    256
#define HID     64
#define HEADS   4
#define OUT_C   64
#define F1      (HEADS * HID)         // 256

// ---------------- scratch (device globals, no allocs) ----------------
__device__ float g_h1[(size_t)N_NODES * F1];
__device__ float g_out1[(size_t)N_NODES * F1];
__device__ float g_h2[(size_t)N_NODES * OUT_C];
__device__ float g_e1s[N_NODES * HEADS];
__device__ float g_e1d[N_NODES * HEADS];
__device__ float g_e2s[N_NODES];
__device__ float g_e2d[N_NODES];
__device__ int   g_cnt[N_NODES];
__device__ int   g_off[N_NODES + 1];
__device__ int   g_rank[E_EDGES];
__device__ int   g_csr[E_TOT];

// ================= CSR build =================
__global__ void initcnt_kernel(int* __restrict__ cnt) {
    int i = blockIdx.x * blockDim.x + threadIdx.x;
    if (i < N_NODES) cnt[i] = 0;
}
__global__ void count_kernel(const int* __restrict__ ei, int* __restrict__ cnt,
                             int* __restrict__ rank) {
    int e = (blockIdx.x * blockDim.x + threadIdx.x) * 4;
    if (e >= E_EDGES) return;
    int4 d4 = *(const int4*)(ei + E_EDGES + e);
    int4 r4;
    r4.x = atomicAdd(&cnt[d4.x], 1);
    r4.y = atomicAdd(&cnt[d4.y], 1);
    r4.z = atomicAdd(&cnt[d4.z], 1);
    r4.w = atomicAdd(&cnt[d4.w], 1);
    *(int4*)(rank + e) = r4;
}
__global__ void __launch_bounds__(1024) scan_kernel(const int* __restrict__ cnt,
                                                    int* __restrict__ off,
                                                    int* __restrict__ csr) {
    __shared__ int wsum[32];
    const int CH = (N_NODES + 1023) / 1024;   // 20
    int tid = threadIdx.x;
    int lane = tid & 31, warp = tid >> 5;
    int base = tid * CH;
    int local[CH];
    int sum = 0;
    #pragma unroll
    for (int i = 0; i < CH; i++) {
        int idx = base + i;
        int v = idx < N_NODES ? (cnt[idx] + 1) : 0;
        local[i] = sum;
        sum += v;
    }
    int inc = sum;
    #pragma unroll
    for (int o = 1; o < 32; o <<= 1) {
        int t = __shfl_up_sync(0xFFFFFFFFu, inc, o);
        if (lane >= o) inc += t;
    }
    if (lane == 31) wsum[warp] = inc;
    __syncthreads();
    if (warp == 0) {
        int w = wsum[lane];
        #pragma unroll
        for (int o = 1; o < 32; o <<= 1) {
            int t = __shfl_up_sync(0xFFFFFFFFu, w, o);
            if (lane >= o) w += t;
        }
        wsum[lane] = w;
    }
    __syncthreads();
    int prev = inc - sum + (warp ? wsum[warp - 1] : 0);
    #pragma unroll
    for (int i = 0; i < CH; i++) {
        int idx = base + i;
        if (idx < N_NODES) {
            int v = prev + local[i];
            off[idx] = v;
            csr[v] = idx;   // self-loop at slot 0
        }
    }
    if (tid == 1023) off[N_NODES] = prev + sum;
}
__global__ void fill_kernel(const int* __restrict__ ei, const int* __restrict__ off,
                            const int* __restrict__ rank, int* __restrict__ csr) {
    int e = (blockIdx.x * blockDim.x + threadIdx.x) * 4;
    if (e >= E_EDGES) return;
    int4 s4 = *(const int4*)(ei + e);
    int4 d4 = *(const int4*)(ei + E_EDGES + e);
    int4 r4 = *(const int4*)(rank + e);
    csr[off[d4.x] + 1 + r4.x] = s4.x;
    csr[off[d4.y] + 1 + r4.y] = s4.y;
    csr[off[d4.z] + 1 + r4.z] = s4.z;
    csr[off[d4.w] + 1 + r4.w] = s4.w;
}

// ---------------- mma.sync bf16 helper ----------------
__device__ __forceinline__ void mma_bf16(float* d, const uint32_t* a,
                                         const uint32_t* b, const float* c) {
    asm volatile(
        "mma.sync.aligned.m16n8k16.row.col.f32.bf16.bf16.f32 "
        "{%0,%1,%2,%3}, {%4,%5,%6,%7}, {%8,%9}, {%10,%11,%12,%13};"
        : "=f"(d[0]), "=f"(d[1]), "=f"(d[2]), "=f"(d[3])
        : "r"(a[0]), "r"(a[1]), "r"(a[2]), "r"(a[3]),
          "r"(b[0]), "r"(b[1]),
          "f"(c[0]), "f"(c[1]), "f"(c[2]), "f"(c[3]));
}

// ---------- layer-1 GEMM on HMMA: BM=128, BN=128, BK=32, bf16 3-MMA split ----------
// grid: x = F1/128 (2), y = M/128. Fused es/ed attention-dot epilogue.
#define ASTR 40   // bf16 row stride (conflict-free for quad pattern)
__global__ void __launch_bounds__(256)
gemm1_mma_kernel(const float* __restrict__ A, const float* __restrict__ W,
                 float* __restrict__ C, int M,
                 const float* __restrict__ a_src, const float* __restrict__ a_dst,
                 float* __restrict__ es, float* __restrict__ ed) {
    __shared__ __nv_bfloat16 Ah[128 * ASTR];
    __shared__ __nv_bfloat16 Al[128 * ASTR];
    __shared__ __nv_bfloat16 Bh[128 * ASTR];
    __shared__ __nv_bfloat16 Bl[128 * ASTR];
    __shared__ float AS[128], AD[128];

    const int tid = threadIdx.x;
    const int w = tid >> 5, lane = tid & 31;
    const int q = lane & 3, r = lane >> 2;
    const int bm = blockIdx.y * 128;
    const int bn = blockIdx.x * 128;
    const int wrow = w * 16;

    if (tid < 128) {
        AS[tid] = a_src[bn + tid];
        AD[tid] = a_dst[bn + tid];
    }

    float acc[16][4];
    #pragma unroll
    for (int t = 0; t < 16; t++)
        #pragma unroll
        for (int j = 0; j < 4; j++) acc[t][j] = 0.f;

    for (int k0 = 0; k0 < IN_C; k0 += 32) {
        // ---- A tile: 128 rows x 32 k, fp32 -> bf16 hi/lo ----
        {
            int row = tid >> 1;
            int kb = (tid & 1) * 16;
            int gr = bm + row;
            #pragma unroll
            for (int j = 0; j < 4; j++) {
                float4 v = make_float4(0.f, 0.f, 0.f, 0.f);
                if (gr < M) v = *(const float4*)(A + (size_t)gr * IN_C + k0 + kb + j * 4);
                __nv_bfloat16 hx = __float2bfloat16(v.x), hy = __float2bfloat16(v.y);
                __nv_bfloat16 hz = __float2bfloat16(v.z), hw = __float2bfloat16(v.w);
                int o = row * ASTR + kb + j * 4;
                *(__nv_bfloat162*)&Ah[o]     = __nv_bfloat162(hx, hy);
                *(__nv_bfloat162*)&Ah[o + 2] = __nv_bfloat162(hz, hw);
                *(__nv_bfloat162*)&Al[o] = __nv_bfloat162(
                    __float2bfloat16(v.x - __bfloat162float(hx)),
                    __float2bfloat16(v.y - __bfloat162float(hy)));
                *(__nv_bfloat162*)&Al[o + 2] = __nv_bfloat162(
                    __float2bfloat16(v.z - __bfloat162float(hz)),
                    __float2bfloat16(v.w - __bfloat162float(hw)));
            }
        }
        // ---- B tile: W^T, n-major [128 n][32 k] ----
        {
            int n = tid & 127;
            int kb = (tid >> 7) * 16;
            int gn = bn + n;
            #pragma unroll
            for (int j = 0; j < 16; j++) {
                float v = W[(size_t)(k0 + kb + j) * F1 + gn];
                __nv_bfloat16 hi = __float2bfloat16(v);
                Bh[n * ASTR + kb + j] = hi;
                Bl[n * ASTR + kb + j] = __float2bfloat16(v - __bfloat162float(hi));
            }
        }
        __syncthreads();
        #pragma unroll
        for (int ks = 0; ks < 2; ks++) {
            int kk = ks * 16;
            uint32_t ah[4], al[4];
            {
                int c0 = kk + q * 2;
                int r0 = (wrow + r) * ASTR, r1 = (wrow + r + 8) * ASTR;
                ah[0] = *(const uint32_t*)&Ah[r0 + c0];
                ah[1] = *(const uint32_t*)&Ah[r1 + c0];
                ah[2] = *(const uint32_t*)&Ah[r0 + c0 + 8];
                ah[3] = *(const uint32_t*)&Ah[r1 + c0 + 8];
                al[0] = *(const uint32_t*)&Al[r0 + c0];
                al[1] = *(const uint32_t*)&Al[r1 + c0];
                al[2] = *(const uint32_t*)&Al[r0 + c0 + 8];
                al[3] = *(const uint32_t*)&Al[r1 + c0 + 8];
            }
            #pragma unroll
            for (int t = 0; t < 16; t++) {
                int nb = (t * 8 + r) * ASTR + kk + q * 2;
                uint32_t bh[2], bl[2];
                bh[0] = *(const uint32_t*)&Bh[nb];
                bh[1] = *(const uint32_t*)&Bh[nb + 8];
                bl[0] = *(const uint32_t*)&Bl[nb];
                bl[1] = *(const uint32_t*)&Bl[nb + 8];
                mma_bf16(acc[t], ah, bh, acc[t]);
                mma_bf16(acc[t], ah, bl, acc[t]);
                mma_bf16(acc[t], al, bh, acc[t]);
            }
        }
        __syncthreads();
    }

    // ---- epilogue: store C + fused attention dots ----
    int row0 = bm + wrow + r;
    int row1 = row0 + 8;
    float sd0[2] = {0.f, 0.f}, sd1[2] = {0.f, 0.f};
    float dd0[2] = {0.f, 0.f}, dd1[2] = {0.f, 0.f};
    #pragma unroll
    for (int t = 0; t < 16; t++) {
        int c0 = t * 8 + q * 2;
        int hh = t >> 3;
        sd0[hh] += acc[t][0] * AS[c0] + acc[t][1] * AS[c0 + 1];
        dd0[hh] += acc[t][0] * AD[c0] + acc[t][1] * AD[c0 + 1];
        sd1[hh] += acc[t][2] * AS[c0] + acc[t][3] * AS[c0 + 1];
        dd1[hh] += acc[t][2] * AD[c0] + acc[t][3] * AD[c0 + 1];
        if (row0 < M)
            *(float2*)(C + (size_t)row0 * F1 + bn + c0) = make_float2(acc[t][0], acc[t][1]);
        if (row1 < M)
            *(float2*)(C + (size_t)row1 * F1 + bn + c0) = make_float2(acc[t][2], acc[t][3]);
    }
    #pragma unroll
    for (int o = 1; o < 4; o <<= 1) {
        #pragma unroll
        for (int hh = 0; hh < 2; hh++) {
            sd0[hh] += __shfl_xor_sync(0xFFFFFFFFu, sd0[hh], o);
            sd1[hh] += __shfl_xor_sync(0xFFFFFFFFu, sd1[hh], o);
            dd0[hh] += __shfl_xor_sync(0xFFFFFFFFu, dd0[hh], o);
            dd1[hh] += __shfl_xor_sync(0xFFFFFFFFu, dd1[hh], o);
        }
    }
    if (q == 0) {
        int hb = blockIdx.x * 2;
        if (row0 < M) {
            es[row0 * HEADS + hb]     = sd0[0];
            es[row0 * HEADS + hb + 1] = sd0[1];
            ed[row0 * HEADS + hb]     = dd0[0];
            ed[row0 * HEADS + hb + 1] = dd0[1];
        }
        if (row1 < M) {
            es[row1 * HEADS + hb]     = sd1[0];
            es[row1 * HEADS + hb + 1] = sd1[1];
            ed[row1 * HEADS + hb]     = dd1[0];
            ed[row1 * HEADS + hb + 1] = dd1[1];
        }
    }
}

// ---------- layer-2 GEMM (scalar f32x2, BN=64) ----------
__device__ __forceinline__ unsigned long long pack2(float lo, float hi) {
    unsigned long long r;
    asm("mov.b64 %0, {%1, %2};" : "=l"(r) : "f"(lo), "f"(hi));
    return r;
}
__device__ __forceinline__ void unpack2(unsigned long long v, float& lo, float& hi) {
    asm("mov.b64 {%0, %1}, %2;" : "=f"(lo), "=f"(hi) : "l"(v));
}
__device__ __forceinline__ unsigned long long fma2(unsigned long long a,
                                                   unsigned long long b,
                                                   unsigned long long c) {
    unsigned long long d;
    asm("fma.rn.f32x2 %0, %1, %2, %3;" : "=l"(d) : "l"(a), "l"(b), "l"(c));
    return d;
}
__global__ void __launch_bounds__(128)
sgemm2_kernel(const float* __restrict__ A, const float* __restrict__ B,
              float* __restrict__ C, int M, int K,
              const float* __restrict__ a_src, const float* __restrict__ a_dst,
              float* __restrict__ es, float* __restrict__ ed) {
    const int N = 64;
    __shared__ float As[16][132];
    __shared__ float Bs[16][68];
    const int bm = blockIdx.y * 128;
    const int tid = threadIdx.x;
    const int tm = (tid >> 3) * 8;
    const int tn = (tid & 7) * 8;

    unsigned long long acc[8][4];
    #pragma unroll
    for (int i = 0; i < 8; i++)
        #pragma unroll
        for (int j = 0; j < 4; j++) acc[i][j] = 0ull;

    for (int k0 = 0; k0 < K; k0 += 16) {
        {
            int r = tid;
            int row = bm + r;
            #pragma unroll
            for (int cc = 0; cc < 4; cc++) {
                int c = cc * 4;
                float4 v = make_float4(0.f, 0.f, 0.f, 0.f);
                if (row < M) v = *(const float4*)(A + (size_t)row * K + k0 + c);
                As[c + 0][r] = v.x; As[c + 1][r] = v.y;
                As[c + 2][r] = v.z; As[c + 3][r] = v.w;
            }
        }
        {
            int r = tid >> 3;
            int c = (tid & 7) * 8;
            const float* src = B + (size_t)(k0 + r) * N + c;
            *(float4*)&Bs[r][c] = *(const float4*)src;
            *(float4*)&Bs[r][c + 4] = *(const float4*)(src + 4);
        }
        __syncthreads();
        #pragma unroll
        for (int kk = 0; kk < 16; kk++) {
            float a[8];
            *(float4*)&a[0] = *(const float4*)&As[kk][tm];
            *(float4*)&a[4] = *(const float4*)&As[kk][tm + 4];
            unsigned long long b2v[4];
            float bl[8];
            *(float4*)&bl[0] = *(const float4*)&Bs[kk][tn];
            *(float4*)&bl[4] = *(const float4*)&Bs[kk][tn + 4];
            #pragma unroll
            for (int j = 0; j < 4; j++) b2v[j] = pack2(bl[2 * j], bl[2 * j + 1]);
            #pragma unroll
            for (int i = 0; i < 8; i++) {
                unsigned long long a2 = pack2(a[i], a[i]);
                #pragma unroll
                for (int j = 0; j < 4; j++) acc[i][j] = fma2(a2, b2v[j], acc[i][j]);
            }
        }
        __syncthreads();
    }

    float aS[8], aD[8];
    #pragma unroll
    for (int j = 0; j < 8; j++) {
        aS[j] = a_src[tn + j];
        aD[j] = a_dst[tn + j];
    }
    #pragma unroll
    for (int i = 0; i < 8; i++) {
        int m = bm + tm + i;
        float o[8];
        #pragma unroll
        for (int j = 0; j < 4; j++) unpack2(acc[i][j], o[2 * j], o[2 * j + 1]);
        if (m < M) {
            float* dst = C + (size_t)m * N + tn;
            *(float4*)dst = *(float4*)&o[0];
            *(float4*)(dst + 4) = *(float4*)&o[4];
        }
        float s = 0.f, dv = 0.f;
        #pragma unroll
        for (int j = 0; j < 8; j++) { s += o[j] * aS[j]; dv += o[j] * aD[j]; }
        #pragma unroll
        for (int o2 = 1; o2 < 8; o2 <<= 1) {
            s  += __shfl_xor_sync(0xFFFFFFFFu, s, o2);
            dv += __shfl_xor_sync(0xFFFFFFFFu, dv, o2);
        }
        if ((tid & 7) == 0 && m < M) {
            es[m] = s;
            ed[m] = dv;
        }
    }
}

// ---------------- layer-1 pull aggregation: warp per (node, head) ----------------
__global__ void agg1_kernel(const int* __restrict__ off, const int* __restrict__ csr,
                            const float* __restrict__ h,
                            const float* __restrict__ es, const float* __restrict__ ed,
                            const float* __restrict__ b1, float* __restrict__ out) {
    int gw = (blockIdx.x * blockDim.x + threadIdx.x) >> 5;
    int lane = threadIdx.x & 31;
    if (gw >= N_NODES * HEADS) return;
    int n = gw >> 2, head = gw & 3;
    int beg = off[n], end = off[n + 1];
    float edn = ed[n * HEADS + head];
    float accx = 0.f, accy = 0.f, zsum = 0.f;
    for (int base = beg; base < end; base += 32) {
        int m = min(32, end - base);
        int sl = 0; float pl = 0.f;
        if (base + lane < end) {
            sl = csr[base + lane];
            float l = es[sl * HEADS + head] + edn;
            l = l > 0.f ? l : 0.2f * l;
            pl = expf(l);
        }
        int j = 0;
        for (; j + 2 <= m; j += 2) {
            int s0 = __shfl_sync(0xFFFFFFFFu, sl, j);
            int s1 = __shfl_sync(0xFFFFFFFFu, sl, j + 1);
            float p0 = __shfl_sync(0xFFFFFFFFu, pl, j);
            float p1 = __shfl_sync(0xFFFFFFFFu, pl, j + 1);
            float2 v0 = *(const float2*)(h + (size_t)s0 * F1 + head * 64 + lane * 2);
            float2 v1 = *(const float2*)(h + (size_t)s1 * F1 + head * 64 + lane * 2);
            zsum += p0 + p1;
            accx += p0 * v0.x + p1 * v1.x;
            accy += p0 * v0.y + p1 * v1.y;
        }
        if (j < m) {
            int s0 = __shfl_sync(0xFFFFFFFFu, sl, j);
            float p0 = __shfl_sync(0xFFFFFFFFu, pl, j);
            float2 v0 = *(const float2*)(h + (size_t)s0 * F1 + head * 64 + lane * 2);
            zsum += p0;
            accx += p0 * v0.x;
            accy += p0 * v0.y;
        }
    }
    float inv = 1.f / zsum;
    int c = head * 64 + lane * 2;
    float o0 = accx * inv + b1[c];
    float o1 = accy * inv + b1[c + 1];
    o0 = o0 > 0.f ? o0 : expm1f(o0);
    o1 = o1 > 0.f ? o1 : expm1f(o1);
    float2 r; r.x = o0; r.y = o1;
    *(float2*)(out + (size_t)n * F1 + c) = r;
}

// ---------------- layer-2 pull aggregation: warp per node ----------------
__global__ void agg2_kernel(const int* __restrict__ off, const int* __restrict__ csr,
                            const float* __restrict__ h2,
                            const float* __restrict__ es, const float* __restrict__ ed,
                            const float* __restrict__ b2, float* __restrict__ out) {
    int n = (blockIdx.x * blockDim.x + threadIdx.x) >> 5;
    int lane = threadIdx.x & 31;
    if (n >= N_NODES) return;
    int beg = off[n], end = off[n + 1];
    float edn = ed[n];
    float accx = 0.f, accy = 0.f, zsum = 0.f;
    for (int base = beg; base < end; base += 32) {
        int m = min(32, end - base);
        int sl = 0; float pl = 0.f;
        if (base + lane < end) {
            sl = csr[base + lane];
            float l = es[sl] + edn;
            l = l > 0.f ? l : 0.2f * l;
            pl = expf(l);
        }
        int j = 0;
        for (; j + 2 <= m; j += 2) {
            int s0 = __shfl_sync(0xFFFFFFFFu, sl, j);
            int s1 = __shfl_sync(0xFFFFFFFFu, sl, j + 1);
            float p0 = __shfl_sync(0xFFFFFFFFu, pl, j);
            float p1 = __shfl_sync(0xFFFFFFFFu, pl, j + 1);
            float2 v0 = *(const float2*)(h2 + (size_t)s0 * OUT_C + lane * 2);
            float2 v1 = *(const float2*)(h2 + (size_t)s1 * OUT_C + lane * 2);
            zsum += p0 + p1;
            accx += p0 * v0.x + p1 * v1.x;
            accy += p0 * v0.y + p1 * v1.y;
        }
        if (j < m) {
            int s0 = __shfl_sync(0xFFFFFFFFu, sl, j);
            float p0 = __shfl_sync(0xFFFFFFFFu, pl, j);
            float2 v0 = *(const float2*)(h2 + (size_t)s0 * OUT_C + lane * 2);
            zsum += p0;
            accx += p0 * v0.x;
            accy += p0 * v0.y;
        }
    }
    float inv = 1.f / zsum;
    float2 r;
    r.x = accx * inv + b2[lane * 2];
    r.y = accy * inv + b2[lane * 2 + 1];
    *(float2*)(out + (size_t)n * OUT_C + lane * 2) = r;
}

extern "C" void kernel_launch(void* const* d_in, const int* in_sizes, int n_in,
                              void* d_out, int out_size) {
    const float* x    = (const float*)d_in[0];
    const int*   ei   = (const int*)d_in[1];
    const float* W1   = (const float*)d_in[2];
    const float* a1s  = (const float*)d_in[3];
    const float* a1d  = (const float*)d_in[4];
    const float* b1   = (const float*)d_in[5];
    const float* W2   = (const float*)d_in[6];
    const float* a2s  = (const float*)d_in[7];
    const float* a2d  = (const float*)d_in[8];
    const float* b2   = (const float*)d_in[9];
    float* out = (float*)d_out;

    float *h1, *out1, *h2, *e1s, *e1d, *e2s, *e2d;
    int *cnt, *off, *rank, *csr;
    cudaGetSymbolAddress((void**)&h1,  g_h1);
    cudaGetSymbolAddress((void**)&out1, g_out1);
    cudaGetSymbolAddress((void**)&h2,  g_h2);
    cudaGetSymbolAddress((void**)&e1s, g_e1s);
    cudaGetSymbolAddress((void**)&e1d, g_e1d);
    cudaGetSymbolAddress((void**)&e2s, g_e2s);
    cudaGetSymbolAddress((void**)&e2d, g_e2d);
    cudaGetSymbolAddress((void**)&cnt, g_cnt);
    cudaGetSymbolAddress((void**)&off, g_off);
    cudaGetSymbolAddress((void**)&rank, g_rank);
    cudaGetSymbolAddress((void**)&csr, g_csr);

    // ---- CSR build (gemm1 stays at launch index 3 for ncu) ----
    initcnt_kernel<<<(N_NODES + 255) / 256, 256>>>(cnt);                       // 0
    count_kernel<<<(E_EDGES / 4 + 255) / 256, 256>>>(ei, cnt, rank);           // 1
    scan_kernel<<<1, 1024>>>(cnt, off, csr);                                   // 2

    // ---- Layer 1 GEMM on HMMA tensor cores (+ fused attention dots) ----
    {
        dim3 grid(F1 / 128, (N_NODES + 127) / 128);
        gemm1_mma_kernel<<<grid, 256>>>(x, W1, h1, N_NODES,                    // 3
                                        a1s, a1d, e1s, e1d);
    }
    fill_kernel<<<(E_EDGES / 4 + 255) / 256, 256>>>(ei, off, rank, csr);       // 4
    agg1_kernel<<<(N_NODES * HEADS * 32 + 255) / 256, 256>>>(off, csr, h1,     // 5
                                                             e1s, e1d, b1, out1);

    // ---- Layer 2 ----
    {
        dim3 grid(1, (N_NODES + 127) / 128);
        sgemm2_kernel<<<grid, 128>>>(out1, W2, h2, N_NODES, F1,                // 6
                                     a2s, a2d, e2s, e2d);
    }
    agg2_kernel<<<(N_NODES * 32 + 255) / 256, 256>>>(off, csr, h2,             // 7
                                                     e2s, e2d, b2, out);
}

// round 10
// speedup vs baseline: 1.6264x; 1.0433x over previous
#include <cuda_runtime.h>
#include <cuda_bf16.h>
#include <cstdint>

#define N_NODES 20000
#define E_EDGES 320000
#define E_TOT   (E_EDGES + N_NODES)
#define IN_C    256
#define HID     64
#define HEADS   4
#define OUT_C   64
#define F1      (HEADS * HID)         // 256

// ---------------- scratch (device globals, no allocs) ----------------
__device__ float g_h1[(size_t)N_NODES * F1];
__device__ float g_out1[(size_t)N_NODES * F1];
__device__ float g_h2[(size_t)N_NODES * OUT_C];
__device__ float g_e1s[N_NODES * HEADS];
__device__ float g_e1d[N_NODES * HEADS];
__device__ float g_e2s[N_NODES];
__device__ float g_e2d[N_NODES];
__device__ int   g_cnt[N_NODES];
__device__ int   g_off[N_NODES + 1];
__device__ int   g_rank[E_EDGES];
__device__ int   g_csr[E_TOT];

// ================= CSR build =================
__global__ void initcnt_kernel(int* __restrict__ cnt) {
    int i = blockIdx.x * blockDim.x + threadIdx.x;
    if (i < N_NODES) cnt[i] = 0;
}
__global__ void count_kernel(const int* __restrict__ ei, int* __restrict__ cnt,
                             int* __restrict__ rank) {
    int e = (blockIdx.x * blockDim.x + threadIdx.x) * 4;
    if (e >= E_EDGES) return;
    int4 d4 = *(const int4*)(ei + E_EDGES + e);
    int4 r4;
    r4.x = atomicAdd(&cnt[d4.x], 1);
    r4.y = atomicAdd(&cnt[d4.y], 1);
    r4.z = atomicAdd(&cnt[d4.z], 1);
    r4.w = atomicAdd(&cnt[d4.w], 1);
    *(int4*)(rank + e) = r4;
}
__global__ void __launch_bounds__(1024) scan_kernel(const int* __restrict__ cnt,
                                                    int* __restrict__ off,
                                                    int* __restrict__ csr) {
    __shared__ int wsum[32];
    const int CH = (N_NODES + 1023) / 1024;   // 20
    int tid = threadIdx.x;
    int lane = tid & 31, warp = tid >> 5;
    int base = tid * CH;
    int local[CH];
    int sum = 0;
    #pragma unroll
    for (int i = 0; i < CH; i++) {
        int idx = base + i;
        int v = idx < N_NODES ? (cnt[idx] + 1) : 0;
        local[i] = sum;
        sum += v;
    }
    int inc = sum;
    #pragma unroll
    for (int o = 1; o < 32; o <<= 1) {
        int t = __shfl_up_sync(0xFFFFFFFFu, inc, o);
        if (lane >= o) inc += t;
    }
    if (lane == 31) wsum[warp] = inc;
    __syncthreads();
    if (warp == 0) {
        int w = wsum[lane];
        #pragma unroll
        for (int o = 1; o < 32; o <<= 1) {
            int t = __shfl_up_sync(0xFFFFFFFFu, w, o);
            if (lane >= o) w += t;
        }
        wsum[lane] = w;
    }
    __syncthreads();
    int prev = inc - sum + (warp ? wsum[warp - 1] : 0);
    #pragma unroll
    for (int i = 0; i < CH; i++) {
        int idx = base + i;
        if (idx < N_NODES) {
            int v = prev + local[i];
            off[idx] = v;
            csr[v] = idx;   // self-loop at slot 0
        }
    }
    if (tid == 1023) off[N_NODES] = prev + sum;
}
__global__ void fill_kernel(const int* __restrict__ ei, const int* __restrict__ off,
                            const int* __restrict__ rank, int* __restrict__ csr) {
    int e = (blockIdx.x * blockDim.x + threadIdx.x) * 4;
    if (e >= E_EDGES) return;
    int4 s4 = *(const int4*)(ei + e);
    int4 d4 = *(const int4*)(ei + E_EDGES + e);
    int4 r4 = *(const int4*)(rank + e);
    csr[off[d4.x] + 1 + r4.x] = s4.x;
    csr[off[d4.y] + 1 + r4.y] = s4.y;
    csr[off[d4.z] + 1 + r4.z] = s4.z;
    csr[off[d4.w] + 1 + r4.w] = s4.w;
}

// ---------------- mma / ldmatrix helpers ----------------
__device__ __forceinline__ void mma_bf16(float* d, const uint32_t* a,
                                         const uint32_t* b, const float* c) {
    asm volatile(
        "mma.sync.aligned.m16n8k16.row.col.f32.bf16.bf16.f32 "
        "{%0,%1,%2,%3}, {%4,%5,%6,%7}, {%8,%9}, {%10,%11,%12,%13};"
        : "=f"(d[0]), "=f"(d[1]), "=f"(d[2]), "=f"(d[3])
        : "r"(a[0]), "r"(a[1]), "r"(a[2]), "r"(a[3]),
          "r"(b[0]), "r"(b[1]),
          "f"(c[0]), "f"(c[1]), "f"(c[2]), "f"(c[3]));
}
__device__ __forceinline__ void ldm_x4(uint32_t* r, uint32_t addr) {
    asm volatile("ldmatrix.sync.aligned.m8n8.x4.shared.b16 {%0,%1,%2,%3}, [%4];"
                 : "=r"(r[0]), "=r"(r[1]), "=r"(r[2]), "=r"(r[3]) : "r"(addr));
}
__device__ __forceinline__ uint32_t smem_u32(const void* p) {
    uint32_t a;
    asm("{ .reg .u64 t; cvta.to.shared.u64 t, %1; cvt.u32.u64 %0, t; }" : "=r"(a) : "l"(p));
    return a;
}

// ---------- layer-1 GEMM on HMMA: BM=128, BN=128, BK=32, bf16 3-MMA split ----------
// grid: x = F1/128 (2), y = M/128. Fused es/ed attention-dot epilogue.
#define ASTR 40   // bf16 row stride: 80B => ldmatrix row addrs hit disjoint banks
__global__ void __launch_bounds__(256)
gemm1_mma_kernel(const float* __restrict__ A, const float* __restrict__ W,
                 float* __restrict__ C, int M,
                 const float* __restrict__ a_src, const float* __restrict__ a_dst,
                 float* __restrict__ es, float* __restrict__ ed) {
    __shared__ __nv_bfloat16 Ah[128 * ASTR];
    __shared__ __nv_bfloat16 Al[128 * ASTR];
    __shared__ __nv_bfloat16 Bh[128 * ASTR];
    __shared__ __nv_bfloat16 Bl[128 * ASTR];
    __shared__ float AS[128], AD[128];

    const int tid = threadIdx.x;
    const int w = tid >> 5, lane = tid & 31;
    const int q = lane & 3, r = lane >> 2;
    const int bm = blockIdx.y * 128;
    const int bn = blockIdx.x * 128;
    const int wrow = w * 16;

    if (tid < 128) {
        AS[tid] = a_src[bn + tid];
        AD[tid] = a_dst[bn + tid];
    }

    // ldmatrix lane-address components (bf16 units)
    const int ln  = lane & 7;
    const int sel = lane >> 3;
    // A frag: matrix sel -> row += (sel&1)*8, k += (sel>>1)*8
    const uint32_t ah_base = smem_u32(Ah);
    const uint32_t al_base = smem_u32(Al);
    const uint32_t bh_base = smem_u32(Bh);
    const uint32_t bl_base = smem_u32(Bl);
    const uint32_t a_off = (uint32_t)(((wrow + ln + (sel & 1) * 8) * ASTR + (sel >> 1) * 8) * 2);
    // B frag for t-pair base t: matrix sel -> n-tile += (sel>>1), k += (sel&1)*8
    const uint32_t b_off = (uint32_t)((((sel >> 1) * 8 + ln) * ASTR + (sel & 1) * 8) * 2);
    const uint32_t b_tstep = (uint32_t)(8 * ASTR * 2);

    float acc[16][4];
    #pragma unroll
    for (int t = 0; t < 16; t++)
        #pragma unroll
        for (int j = 0; j < 4; j++) acc[t][j] = 0.f;

    for (int k0 = 0; k0 < IN_C; k0 += 32) {
        // ---- A tile: 128 rows x 32 k, fp32 -> bf16 hi/lo ----
        {
            int row = tid >> 1;
            int kb = (tid & 1) * 16;
            int gr = bm + row;
            #pragma unroll
            for (int j = 0; j < 4; j++) {
                float4 v = make_float4(0.f, 0.f, 0.f, 0.f);
                if (gr < M) v = *(const float4*)(A + (size_t)gr * IN_C + k0 + kb + j * 4);
                __nv_bfloat16 hx = __float2bfloat16(v.x), hy = __float2bfloat16(v.y);
                __nv_bfloat16 hz = __float2bfloat16(v.z), hw = __float2bfloat16(v.w);
                int o = row * ASTR + kb + j * 4;
                *(__nv_bfloat162*)&Ah[o]     = __nv_bfloat162(hx, hy);
                *(__nv_bfloat162*)&Ah[o + 2] = __nv_bfloat162(hz, hw);
                *(__nv_bfloat162*)&Al[o] = __nv_bfloat162(
                    __float2bfloat16(v.x - __bfloat162float(hx)),
                    __float2bfloat16(v.y - __bfloat162float(hy)));
                *(__nv_bfloat162*)&Al[o + 2] = __nv_bfloat162(
                    __float2bfloat16(v.z - __bfloat162float(hz)),
                    __float2bfloat16(v.w - __bfloat162float(hw)));
            }
        }
        // ---- B tile: W^T, n-major [128 n][32 k] ----
        {
            int n = tid & 127;
            int kb = (tid >> 7) * 16;
            int gn = bn + n;
            #pragma unroll
            for (int j = 0; j < 16; j++) {
                float v = W[(size_t)(k0 + kb + j) * F1 + gn];
                __nv_bfloat16 hi = __float2bfloat16(v);
                Bh[n * ASTR + kb + j] = hi;
                Bl[n * ASTR + kb + j] = __float2bfloat16(v - __bfloat162float(hi));
            }
        }
        __syncthreads();
        #pragma unroll
        for (int ks = 0; ks < 2; ks++) {
            const uint32_t koff = (uint32_t)(ks * 16 * 2);   // bytes
            uint32_t ah[4], al[4];
            ldm_x4(ah, ah_base + a_off + koff);
            ldm_x4(al, al_base + a_off + koff);
            #pragma unroll
            for (int tp = 0; tp < 8; tp++) {
                const int t = tp * 2;
                uint32_t bh4[4], bl4[4];
                uint32_t ba = b_off + koff + (uint32_t)t * b_tstep;
                ldm_x4(bh4, bh_base + ba);
                ldm_x4(bl4, bl_base + ba);
                mma_bf16(acc[t],     ah, &bh4[0], acc[t]);
                mma_bf16(acc[t],     ah, &bl4[0], acc[t]);
                mma_bf16(acc[t],     al, &bh4[0], acc[t]);
                mma_bf16(acc[t + 1], ah, &bh4[2], acc[t + 1]);
                mma_bf16(acc[t + 1], ah, &bl4[2], acc[t + 1]);
                mma_bf16(acc[t + 1], al, &bh4[2], acc[t + 1]);
            }
        }
        __syncthreads();
    }

    // ---- epilogue: store C + fused attention dots ----
    int row0 = bm + wrow + r;
    int row1 = row0 + 8;
    float sd0[2] = {0.f, 0.f}, sd1[2] = {0.f, 0.f};
    float dd0[2] = {0.f, 0.f}, dd1[2] = {0.f, 0.f};
    #pragma unroll
    for (int t = 0; t < 16; t++) {
        int c0 = t * 8 + q * 2;
        int hh = t >> 3;
        sd0[hh] += acc[t][0] * AS[c0] + acc[t][1] * AS[c0 + 1];
        dd0[hh] += acc[t][0] * AD[c0] + acc[t][1] * AD[c0 + 1];
        sd1[hh] += acc[t][2] * AS[c0] + acc[t][3] * AS[c0 + 1];
        dd1[hh] += acc[t][2] * AD[c0] + acc[t][3] * AD[c0 + 1];
        if (row0 < M)
            *(float2*)(C + (size_t)row0 * F1 + bn + c0) = make_float2(acc[t][0], acc[t][1]);
        if (row1 < M)
            *(float2*)(C + (size_t)row1 * F1 + bn + c0) = make_float2(acc[t][2], acc[t][3]);
    }
    #pragma unroll
    for (int o = 1; o < 4; o <<= 1) {
        #pragma unroll
        for (int hh = 0; hh < 2; hh++) {
            sd0[hh] += __shfl_xor_sync(0xFFFFFFFFu, sd0[hh], o);
            sd1[hh] += __shfl_xor_sync(0xFFFFFFFFu, sd1[hh], o);
            dd0[hh] += __shfl_xor_sync(0xFFFFFFFFu, dd0[hh], o);
            dd1[hh] += __shfl_xor_sync(0xFFFFFFFFu, dd1[hh], o);
        }
    }
    if (q == 0) {
        int hb = blockIdx.x * 2;
        if (row0 < M) {
            es[row0 * HEADS + hb]     = sd0[0];
            es[row0 * HEADS + hb + 1] = sd0[1];
            ed[row0 * HEADS + hb]     = dd0[0];
            ed[row0 * HEADS + hb + 1] = dd0[1];
        }
        if (row1 < M) {
            es[row1 * HEADS + hb]     = sd1[0];
            es[row1 * HEADS + hb + 1] = sd1[1];
            ed[row1 * HEADS + hb]     = dd1[0];
            ed[row1 * HEADS + hb + 1] = dd1[1];
        }
    }
}

// ---------- layer-2 GEMM (scalar f32x2, BN=64) ----------
__device__ __forceinline__ unsigned long long pack2(float lo, float hi) {
    unsigned long long r;
    asm("mov.b64 %0, {%1, %2};" : "=l"(r) : "f"(lo), "f"(hi));
    return r;
}
__device__ __forceinline__ void unpack2(unsigned long long v, float& lo, float& hi) {
    asm("mov.b64 {%0, %1}, %2;" : "=f"(lo), "=f"(hi) : "l"(v));
}
__device__ __forceinline__ unsigned long long fma2(unsigned long long a,
                                                   unsigned long long b,
                                                   unsigned long long c) {
    unsigned long long d;
    asm("fma.rn.f32x2 %0, %1, %2, %3;" : "=l"(d) : "l"(a), "l"(b), "l"(c));
    return d;
}
__global__ void __launch_bounds__(128)
sgemm2_kernel(const float* __restrict__ A, const float* __restrict__ B,
              float* __restrict__ C, int M, int K,
              const float* __restrict__ a_src, const float* __restrict__ a_dst,
              float* __restrict__ es, float* __restrict__ ed) {
    const int N = 64;
    __shared__ float As[16][132];
    __shared__ float Bs[16][68];
    const int bm = blockIdx.y * 128;
    const int tid = threadIdx.x;
    const int tm = (tid >> 3) * 8;
    const int tn = (tid & 7) * 8;

    unsigned long long acc[8][4];
    #pragma unroll
    for (int i = 0; i < 8; i++)
        #pragma unroll
        for (int j = 0; j < 4; j++) acc[i][j] = 0ull;

    for (int k0 = 0; k0 < K; k0 += 16) {
        {
            int r = tid;
            int row = bm + r;
            #pragma unroll
            for (int cc = 0; cc < 4; cc++) {
                int c = cc * 4;
                float4 v = make_float4(0.f, 0.f, 0.f, 0.f);
                if (row < M) v = *(const float4*)(A + (size_t)row * K + k0 + c);
                As[c + 0][r] = v.x; As[c + 1][r] = v.y;
                As[c + 2][r] = v.z; As[c + 3][r] = v.w;
            }
        }
        {
            int r = tid >> 3;
            int c = (tid & 7) * 8;
            const float* src = B + (size_t)(k0 + r) * N + c;
            *(float4*)&Bs[r][c] = *(const float4*)src;
            *(float4*)&Bs[r][c + 4] = *(const float4*)(src + 4);
        }
        __syncthreads();
        #pragma unroll
        for (int kk = 0; kk < 16; kk++) {
            float a[8];
            *(float4*)&a[0] = *(const float4*)&As[kk][tm];
            *(float4*)&a[4] = *(const float4*)&As[kk][tm + 4];
            unsigned long long b2v[4];
            float bl[8];
            *(float4*)&bl[0] = *(const float4*)&Bs[kk][tn];
            *(float4*)&bl[4] = *(const float4*)&Bs[kk][tn + 4];
            #pragma unroll
            for (int j = 0; j < 4; j++) b2v[j] = pack2(bl[2 * j], bl[2 * j + 1]);
            #pragma unroll
            for (int i = 0; i < 8; i++) {
                unsigned long long a2 = pack2(a[i], a[i]);
                #pragma unroll
                for (int j = 0; j < 4; j++) acc[i][j] = fma2(a2, b2v[j], acc[i][j]);
            }
        }
        __syncthreads();
    }

    float aS[8], aD[8];
    #pragma unroll
    for (int j = 0; j < 8; j++) {
        aS[j] = a_src[tn + j];
        aD[j] = a_dst[tn + j];
    }
    #pragma unroll
    for (int i = 0; i < 8; i++) {
        int m = bm + tm + i;
        float o[8];
        #pragma unroll
        for (int j = 0; j < 4; j++) unpack2(acc[i][j], o[2 * j], o[2 * j + 1]);
        if (m < M) {
            float* dst = C + (size_t)m * N + tn;
            *(float4*)dst = *(float4*)&o[0];
            *(float4*)(dst + 4) = *(float4*)&o[4];
        }
        float s = 0.f, dv = 0.f;
        #pragma unroll
        for (int j = 0; j < 8; j++) { s += o[j] * aS[j]; dv += o[j] * aD[j]; }
        #pragma unroll
        for (int o2 = 1; o2 < 8; o2 <<= 1) {
            s  += __shfl_xor_sync(0xFFFFFFFFu, s, o2);
            dv += __shfl_xor_sync(0xFFFFFFFFu, dv, o2);
        }
        if ((tid & 7) == 0 && m < M) {
            es[m] = s;
            ed[m] = dv;
        }
    }
}

// ---------------- layer-1 pull aggregation: warp per (node, head) ----------------
__global__ void agg1_kernel(const int* __restrict__ off, const int* __restrict__ csr,
                            const float* __restrict__ h,
                            const float* __restrict__ es, const float* __restrict__ ed,
                            const float* __restrict__ b1, float* __restrict__ out) {
    int gw = (blockIdx.x * blockDim.x + threadIdx.x) >> 5;
    int lane = threadIdx.x & 31;
    if (gw >= N_NODES * HEADS) return;
    int n = gw >> 2, head = gw & 3;
    int beg = off[n], end = off[n + 1];
    float edn = ed[n * HEADS + head];
    float accx = 0.f, accy = 0.f, zsum = 0.f;
    for (int base = beg; base < end; base += 32) {
        int m = min(32, end - base);
        int sl = 0; float pl = 0.f;
        if (base + lane < end) {
            sl = csr[base + lane];
            float l = es[sl * HEADS + head] + edn;
            l = l > 0.f ? l : 0.2f * l;
            pl = expf(l);
        }
        int j = 0;
        for (; j + 2 <= m; j += 2) {
            int s0 = __shfl_sync(0xFFFFFFFFu, sl, j);
            int s1 = __shfl_sync(0xFFFFFFFFu, sl, j + 1);
            float p0 = __shfl_sync(0xFFFFFFFFu, pl, j);
            float p1 = __shfl_sync(0xFFFFFFFFu, pl, j + 1);
            float2 v0 = *(const float2*)(h + (size_t)s0 * F1 + head * 64 + lane * 2);
            float2 v1 = *(const float2*)(h + (size_t)s1 * F1 + head * 64 + lane * 2);
            zsum += p0 + p1;
            accx += p0 * v0.x + p1 * v1.x;
            accy += p0 * v0.y + p1 * v1.y;
        }
        if (j < m) {
            int s0 = __shfl_sync(0xFFFFFFFFu, sl, j);
            float p0 = __shfl_sync(0xFFFFFFFFu, pl, j);
            float2 v0 = *(const float2*)(h + (size_t)s0 * F1 + head * 64 + lane * 2);
            zsum += p0;
            accx += p0 * v0.x;
            accy += p0 * v0.y;
        }
    }
    float inv = 1.f / zsum;
    int c = head * 64 + lane * 2;
    float o0 = accx * inv + b1[c];
    float o1 = accy * inv + b1[c + 1];
    o0 = o0 > 0.f ? o0 : expm1f(o0);
    o1 = o1 > 0.f ? o1 : expm1f(o1);
    float2 r; r.x = o0; r.y = o1;
    *(float2*)(out + (size_t)n * F1 + c) = r;
}

// ---------------- layer-2 pull aggregation: warp per node ----------------
__global__ void agg2_kernel(const int* __restrict__ off, const int* __restrict__ csr,
                            const float* __restrict__ h2,
                            const float* __restrict__ es, const float* __restrict__ ed,
                            const float* __restrict__ b2, float* __restrict__ out) {
    int n = (blockIdx.x * blockDim.x + threadIdx.x) >> 5;
    int lane = threadIdx.x & 31;
    if (n >= N_NODES) return;
    int beg = off[n], end = off[n + 1];
    float edn = ed[n];
    float accx = 0.f, accy = 0.f, zsum = 0.f;
    for (int base = beg; base < end; base += 32) {
        int m = min(32, end - base);
        int sl = 0; float pl = 0.f;
        if (base + lane < end) {
            sl = csr[base + lane];
            float l = es[sl] + edn;
            l = l > 0.f ? l : 0.2f * l;
            pl = expf(l);
        }
        int j = 0;
        for (; j + 2 <= m; j += 2) {
            int s0 = __shfl_sync(0xFFFFFFFFu, sl, j);
            int s1 = __shfl_sync(0xFFFFFFFFu, sl, j + 1);
            float p0 = __shfl_sync(0xFFFFFFFFu, pl, j);
            float p1 = __shfl_sync(0xFFFFFFFFu, pl, j + 1);
            float2 v0 = *(const float2*)(h2 + (size_t)s0 * OUT_C + lane * 2);
            float2 v1 = *(const float2*)(h2 + (size_t)s1 * OUT_C + lane * 2);
            zsum += p0 + p1;
            accx += p0 * v0.x + p1 * v1.x;
            accy += p0 * v0.y + p1 * v1.y;
        }
        if (j < m) {
            int s0 = __shfl_sync(0xFFFFFFFFu, sl, j);
            float p0 = __shfl_sync(0xFFFFFFFFu, pl, j);
            float2 v0 = *(const float2*)(h2 + (size_t)s0 * OUT_C + lane * 2);
            zsum += p0;
            accx += p0 * v0.x;
            accy += p0 * v0.y;
        }
    }
    float inv = 1.f / zsum;
    float2 r;
    r.x = accx * inv + b2[lane * 2];
    r.y = accy * inv + b2[lane * 2 + 1];
    *(float2*)(out + (size_t)n * OUT_C + lane * 2) = r;
}

extern "C" void kernel_launch(void* const* d_in, const int* in_sizes, int n_in,
                              void* d_out, int out_size) {
    const float* x    = (const float*)d_in[0];
    const int*   ei   = (const int*)d_in[1];
    const float* W1   = (const float*)d_in[2];
    const float* a1s  = (const float*)d_in[3];
    const float* a1d  = (const float*)d_in[4];
    const float* b1   = (const float*)d_in[5];
    const float* W2   = (const float*)d_in[6];
    const float* a2s  = (const float*)d_in[7];
    const float* a2d  = (const float*)d_in[8];
    const float* b2   = (const float*)d_in[9];
    float* out = (float*)d_out;

    float *h1, *out1, *h2, *e1s, *e1d, *e2s, *e2d;
    int *cnt, *off, *rank, *csr;
    cudaGetSymbolAddress((void**)&h1,  g_h1);
    cudaGetSymbolAddress((void**)&out1, g_out1);
    cudaGetSymbolAddress((void**)&h2,  g_h2);
    cudaGetSymbolAddress((void**)&e1s, g_e1s);
    cudaGetSymbolAddress((void**)&e1d, g_e1d);
    cudaGetSymbolAddress((void**)&e2s, g_e2s);
    cudaGetSymbolAddress((void**)&e2d, g_e2d);
    cudaGetSymbolAddress((void**)&cnt, g_cnt);
    cudaGetSymbolAddress((void**)&off, g_off);
    cudaGetSymbolAddress((void**)&rank, g_rank);
    cudaGetSymbolAddress((void**)&csr, g_csr);

    // ---- CSR build (gemm1 stays at launch index 3 for ncu) ----
    initcnt_kernel<<<(N_NODES + 255) / 256, 256>>>(cnt);                       // 0
    count_kernel<<<(E_EDGES / 4 + 255) / 256, 256>>>(ei, cnt, rank);           // 1
    scan_kernel<<<1, 1024>>>(cnt, off, csr);                                   // 2

    // ---- Layer 1 GEMM on HMMA tensor cores (+ fused attention dots) ----
    {
        dim3 grid(F1 / 128, (N_NODES + 127) / 128);
        gemm1_mma_kernel<<<grid, 256>>>(x, W1, h1, N_NODES,                    // 3
                                        a1s, a1d, e1s, e1d);
    }
    fill_kernel<<<(E_EDGES / 4 + 255) / 256, 256>>>(ei, off, rank, csr);       // 4
    agg1_kernel<<<(N_NODES * HEADS * 32 + 255) / 256, 256>>>(off, csr, h1,     // 5
                                                             e1s, e1d, b1, out1);

    // ---- Layer 2 ----
    {
        dim3 grid(1, (N_NODES + 127) / 128);
        sgemm2_kernel<<<grid, 128>>>(out1, W2, h2, N_NODES, F1,                // 6
                                     a2s, a2d, e2s, e2d);
    }
    agg2_kernel<<<(N_NODES * 32 + 255) / 256, 256>>>(off, csr, h2,             // 7
                                                     e2s, e2d, b2, out);
}